// round 14
// baseline (speedup 1.0000x reference)
#include <cuda_runtime.h>
#include <math.h>
#include <stdint.h>

// Problem constants (fixed shapes from setup_inputs)
#define NTOK 2048
#define CDIM 1024
#define HEADS 16
#define DH 64
#define FF 4096
#define NSRC 1024   // NTOK/2

// ---------------- scratch (device globals; no allocation allowed) ------------
__device__ float g_h    [NTOK*CDIM];
__device__ float g_hr   [NTOK*CDIM];    // tf32-rounded h (GEMM input)
__device__ float g_qkv  [NTOK*3*CDIM];  // tf32-rounded (QKV GEMM RND=1)
__device__ float g_wkavg[CDIM*DH];
__device__ float g_mpart[8*NTOK*DH];
__device__ float g_nmet [NTOK*DH];
__device__ float g_xa   [NTOK*CDIM];    // rounded at attn epilogue
__device__ float g_x1   [NTOK*CDIM];
__device__ int   g_mask [NSRC];
__device__ int   g_node [NSRC];
__device__ int   g_pref [NSRC];
__device__ int   g_nUnm [1];
__device__ float g_outx [NTOK*CDIM];
__device__ float g_outs [NTOK];
__device__ float g_x2   [NTOK*CDIM];
__device__ float g_h2   [NTOK*CDIM];    // rounded at fused div+LN2
__device__ float g_ff   [NTOK*FF];      // rounded at fc1 epilogue
// tf32-rounded weight copies
__device__ float g_wqkv [CDIM*3*CDIM];
__device__ float g_wproj[CDIM*CDIM];
__device__ float g_wfc1 [CDIM*FF];
__device__ float g_wfc2 [FF*CDIM];

// ---------------- helpers ----------------------------------------------------
__device__ __forceinline__ uint32_t f2tf32(float v) {
    uint32_t r;
    asm("cvt.rna.tf32.f32 %0, %1;" : "=r"(r) : "f"(v));
    return r;
}
__device__ __forceinline__ float rnd_tf32(float v) {
    return __uint_as_float(f2tf32(v));
}

__device__ __forceinline__ void mma_tf32(float c[4], const uint32_t a[4],
                                         const uint32_t b[2]) {
    asm volatile(
        "mma.sync.aligned.m16n8k8.row.col.f32.tf32.tf32.f32 "
        "{%0,%1,%2,%3}, {%4,%5,%6,%7}, {%8,%9}, {%0,%1,%2,%3};\n"
        : "+f"(c[0]), "+f"(c[1]), "+f"(c[2]), "+f"(c[3])
        : "r"(a[0]), "r"(a[1]), "r"(a[2]), "r"(a[3]), "r"(b[0]), "r"(b[1]));
}

// ldmatrix x4: loads a 16x8 tf32 tile (viewed as b16 pairs) -> A fragment
__device__ __forceinline__ void ldsm_x4(uint32_t r[4], uint32_t addr) {
    asm volatile("ldmatrix.sync.aligned.m8n8.x4.shared.b16 {%0,%1,%2,%3}, [%4];"
        : "=r"(r[0]), "=r"(r[1]), "=r"(r[2]), "=r"(r[3]) : "r"(addr));
}
// ldmatrix x2: loads an 8x8 tf32 tile -> B fragment (g-row, qd-col pattern)
__device__ __forceinline__ void ldsm_x2(uint32_t r[2], uint32_t addr) {
    asm volatile("ldmatrix.sync.aligned.m8n8.x2.shared.b16 {%0,%1}, [%2];"
        : "=r"(r[0]), "=r"(r[1]) : "r"(addr));
}

__device__ __forceinline__ void cp_async16(uint32_t dst, const void* src, int szbytes) {
    asm volatile("cp.async.cg.shared.global [%0], [%1], 16, %2;\n"
                 :: "r"(dst), "l"(src), "r"(szbytes));
}
__device__ __forceinline__ void cp_commit() {
    asm volatile("cp.async.commit_group;\n");
}
template <int N>
__device__ __forceinline__ void cp_wait() {
    asm volatile("cp.async.wait_group %0;\n" :: "n"(N));
}

__device__ __forceinline__ float gelu_exact(float v) {
    return 0.5f * v * (1.0f + erff(v * 0.70710678118654752440f));
}

// ---------------- fused tf32 pre-rounding of all four weight buffers ---------
#define N4_QKV (CDIM*3*CDIM/4)
#define N4_PRJ (CDIM*CDIM/4)
#define N4_FC1 (CDIM*FF/4)
#define N4_FC2 (FF*CDIM/4)
#define N4_ALL (N4_QKV + N4_PRJ + N4_FC1 + N4_FC2)

__global__ __launch_bounds__(256) void round4_kernel(
    const float* __restrict__ w0, const float* __restrict__ w1,
    const float* __restrict__ w2, const float* __restrict__ w3)
{
    int i = blockIdx.x * 256 + threadIdx.x;
    if (i >= N4_ALL) return;
    const float4* src; float4* dst; int off;
    if (i < N4_QKV) {
        src = (const float4*)w0; dst = (float4*)g_wqkv; off = i;
    } else if (i < N4_QKV + N4_PRJ) {
        src = (const float4*)w1; dst = (float4*)g_wproj; off = i - N4_QKV;
    } else if (i < N4_QKV + N4_PRJ + N4_FC1) {
        src = (const float4*)w2; dst = (float4*)g_wfc1; off = i - N4_QKV - N4_PRJ;
    } else {
        src = (const float4*)w3; dst = (float4*)g_wfc2; off = i - N4_QKV - N4_PRJ - N4_FC1;
    }
    float4 v = src[off];
    v.x = rnd_tf32(v.x); v.y = rnd_tf32(v.y);
    v.z = rnd_tf32(v.z); v.w = rnd_tf32(v.w);
    dst[off] = v;
}

// ---------------- layernorm (exact + rounded outputs) ------------------------
__global__ __launch_bounds__(256) void ln_kernel(
    const float* __restrict__ x, const float* __restrict__ g,
    const float* __restrict__ b, float* __restrict__ out,
    float* __restrict__ out_r, int M)
{
    int row = blockIdx.x;
    if (row >= M) return;
    const float* xr = x + (size_t)row * CDIM;
    int tid = threadIdx.x;
    float v[4];
    float s = 0.f, sq = 0.f;
#pragma unroll
    for (int t = 0; t < 4; t++) {
        float vv = xr[tid + t*256];
        v[t] = vv; s += vv; sq += vv*vv;
    }
    __shared__ float rs[256], rq[256];
    rs[tid] = s; rq[tid] = sq;
    __syncthreads();
    for (int off = 128; off > 0; off >>= 1) {
        if (tid < off) { rs[tid] += rs[tid+off]; rq[tid] += rq[tid+off]; }
        __syncthreads();
    }
    float mean = rs[0] * (1.f/CDIM);
    float var  = rq[0] * (1.f/CDIM) - mean*mean;
    float rstd = rsqrtf(var + 1e-5f);
#pragma unroll
    for (int t = 0; t < 4; t++) {
        int c = tid + t*256;
        float o = (v[t] - mean) * rstd * g[c] + b[c];
        if (out)   out  [(size_t)row * CDIM + c] = o;
        if (out_r) out_r[(size_t)row * CDIM + c] = rnd_tf32(o);
    }
}

// ---------------- fused x2 = outx/size, then LN2 -> rounded h2 ----------------
__global__ __launch_bounds__(256) void divln_kernel(
    const float* __restrict__ g, const float* __restrict__ b, int M)
{
    int row = blockIdx.x;
    if (row >= M) return;
    int tid = threadIdx.x;
    float sdiv = g_outs[row];
    float v[4];
    float s = 0.f, sq = 0.f;
#pragma unroll
    for (int t = 0; t < 4; t++) {
        float vv = g_outx[(size_t)row * CDIM + tid + t*256] / sdiv;
        v[t] = vv; s += vv; sq += vv*vv;
        g_x2[(size_t)row * CDIM + tid + t*256] = vv;
    }
    __shared__ float rs[256], rq[256];
    rs[tid] = s; rq[tid] = sq;
    __syncthreads();
    for (int off = 128; off > 0; off >>= 1) {
        if (tid < off) { rs[tid] += rs[tid+off]; rq[tid] += rq[tid+off]; }
        __syncthreads();
    }
    float mean = rs[0] * (1.f/CDIM);
    float var  = rq[0] * (1.f/CDIM) - mean*mean;
    float rstd = rsqrtf(var + 1e-5f);
#pragma unroll
    for (int t = 0; t < 4; t++) {
        int c = tid + t*256;
        float o = (v[t] - mean) * rstd * g[c] + b[c];
        g_h2[(size_t)row * CDIM + c] = rnd_tf32(o);
    }
}

// ---------------- TF32 tensor-core GEMM, cp.async 3-stage, 64x64 warp tiles --
// A-fragments via ldmatrix.x4 (1 instr vs 16 LDS per ks); B stays LDS
// (its (qd-row, g-col) pattern is transposed; 32-bit ldmatrix has no .trans).
#define GSTAGES 3
#define AS_WORDS (GSTAGES*128*20)
#define BS_WORDS (GSTAGES*16*136)
#define GEMM_SMEM ((AS_WORDS + BS_WORDS) * 4)

template <int EPI, int RND>
__global__ __launch_bounds__(128, 3) void gemm_tf32(
    const float* __restrict__ A, const float* __restrict__ B,
    const float* __restrict__ bias, const float* __restrict__ res,
    float* __restrict__ C, int M, int N, int K)
{
    extern __shared__ uint32_t gsm[];
    uint32_t* As = gsm;              // [s][128][20]
    uint32_t* Bs = gsm + AS_WORDS;   // [s][16][136]

    int tid  = threadIdx.x;
    int lane = tid & 31, wid = tid >> 5;   // 4 warps
    int wm = wid >> 1, wn = wid & 1;       // 2x2
    int g  = lane >> 2, qd = lane & 3;
    int m0 = blockIdx.y * 128, n0 = blockIdx.x * 128;

    // per-lane ldmatrix address components (A tile, pitch 20 words):
    // row-within-tile = ((lane>>3)&1)*8 + (lane&7); col offset = (lane>>4)*4
    int lrow = ((lane >> 3) & 1) * 8 + (lane & 7);
    int lcol = (lane >> 4) * 4;

    float acc[4][8][4];
#pragma unroll
    for (int i = 0; i < 4; i++)
#pragma unroll
        for (int j = 0; j < 8; j++)
#pragma unroll
            for (int r = 0; r < 4; r++) acc[i][j][r] = 0.f;

    const int nT = K >> 4;

    int ar[4], ac[4], br[4], bc[4], aSz[4];
#pragma unroll
    for (int u = 0; u < 4; u++) {
        int idx = u*128 + tid;
        ar[u] = idx >> 2;  ac[u] = (idx & 3) * 4;
        br[u] = idx >> 5;  bc[u] = (idx & 31) * 4;
        aSz[u] = (m0 + ar[u] < M) ? 16 : 0;
    }
    uint32_t asBase = (uint32_t)__cvta_generic_to_shared(As);
    uint32_t bsBase = (uint32_t)__cvta_generic_to_shared(Bs);
    // lane-constant byte offset within A tile for ldmatrix
    uint32_t aLane = (uint32_t)(((wm*64 + lrow) * 20 + lcol) * 4);

#pragma unroll
    for (int t = 0; t < GSTAGES-1; t++) {
        int k0 = t * 16;
#pragma unroll
        for (int u = 0; u < 4; u++) {
            cp_async16(asBase + (uint32_t)(((t*128 + ar[u])*20 + ac[u]) * 4),
                       A + (size_t)(m0 + ar[u]) * K + k0 + ac[u], aSz[u]);
            cp_async16(bsBase + (uint32_t)(((t*16 + br[u])*136 + bc[u]) * 4),
                       B + (size_t)(k0 + br[u]) * N + n0 + bc[u], 16);
        }
        cp_commit();
    }

    for (int t = 0; t < nT; t++) {
        cp_wait<GSTAGES-2>();
        __syncthreads();

        int nxt = t + GSTAGES - 1;
        if (nxt < nT) {
            int s  = nxt % GSTAGES;
            int k0 = nxt * 16;
#pragma unroll
            for (int u = 0; u < 4; u++) {
                cp_async16(asBase + (uint32_t)(((s*128 + ar[u])*20 + ac[u]) * 4),
                           A + (size_t)(m0 + ar[u]) * K + k0 + ac[u], aSz[u]);
                cp_async16(bsBase + (uint32_t)(((s*16 + br[u])*136 + bc[u]) * 4),
                           B + (size_t)(k0 + br[u]) * N + n0 + bc[u], 16);
            }
        }
        cp_commit();

        uint32_t aStage = asBase + (uint32_t)((t % GSTAGES) * 128 * 20 * 4) + aLane;
        const uint32_t* Bb = Bs + (t % GSTAGES) * 16 * 136;
#pragma unroll
        for (int ks = 0; ks < 2; ks++) {
            int kb = ks * 8;
            uint32_t af[4][4], bf[8][2];
#pragma unroll
            for (int mf = 0; mf < 4; mf++)
                ldsm_x4(af[mf], aStage + (uint32_t)((mf*16*20 + kb) * 4));
#pragma unroll
            for (int nf = 0; nf < 8; nf++) {
                int c = wn*64 + nf*8 + g;
                bf[nf][0] = Bb[(kb + qd    )*136 + c];
                bf[nf][1] = Bb[(kb + qd + 4)*136 + c];
            }
#pragma unroll
            for (int mf = 0; mf < 4; mf++)
#pragma unroll
                for (int nf = 0; nf < 8; nf++)
                    mma_tf32(acc[mf][nf], af[mf], bf[nf]);
        }
    }

#pragma unroll
    for (int mf = 0; mf < 4; mf++) {
        int rbase = m0 + wm*64 + mf*16 + g;
#pragma unroll
        for (int half = 0; half < 2; half++) {
            int row = rbase + half*8;
            if (row >= M) continue;
#pragma unroll
            for (int nf = 0; nf < 8; nf++) {
                int col = n0 + wn*64 + nf*8 + 2*qd;
                float v0 = acc[mf][nf][half*2 + 0];
                float v1 = acc[mf][nf][half*2 + 1];
                if (EPI >= 1) { v0 += bias[col]; v1 += bias[col+1]; }
                if (EPI == 2) { v0 = gelu_exact(v0); v1 = gelu_exact(v1); }
                if (EPI == 3) {
                    v0 += res[(size_t)row * N + col];
                    v1 += res[(size_t)row * N + col + 1];
                }
                if (RND) { v0 = rnd_tf32(v0); v1 = rnd_tf32(v1); }
                float2 o; o.x = v0; o.y = v1;
                *(float2*)(C + (size_t)row * N + col) = o;
            }
        }
    }
}

// ---------------- fp32 merge-metric path (exactness firewall) ----------------
__global__ __launch_bounds__(256) void wkavg_kernel(const float* __restrict__ qkv_w)
{
    int idx = blockIdx.x * 256 + threadIdx.x;
    if (idx >= CDIM*DH) return;
    int c = idx >> 6, d = idx & 63;
    const float* base = qkv_w + (size_t)c * (3*CDIM) + CDIM + d;
    float s = 0.f;
#pragma unroll
    for (int h = 0; h < HEADS; h++) s += base[h * DH];
    g_wkavg[idx] = s * (1.f / HEADS);
}

// partial metric = h @ wkavg over K chunk of 128  (split-K x8, fp32 SIMT)
__global__ __launch_bounds__(256) void metric_gemm_kernel()
{
    __shared__ float AsT[32][68];   // [k][tok]
    __shared__ float Bs [32][68];   // [k][d]
    int tid = threadIdx.x;
    int tx = tid & 15, ty = tid >> 4;
    int m0 = blockIdx.x * 64;
    int kb = blockIdx.y * 128;

    float acc[4][4];
#pragma unroll
    for (int i = 0; i < 4; i++)
#pragma unroll
        for (int j = 0; j < 4; j++) acc[i][j] = 0.f;

    for (int k0 = kb; k0 < kb + 128; k0 += 32) {
        __syncthreads();
#pragma unroll
        for (int u = 0; u < 2; u++) {
            int idx = tid*2 + u;
            int tok = idx >> 3, kc = (idx & 7) * 4;
            float4 v = *(const float4*)(g_h + (size_t)(m0 + tok) * CDIM + k0 + kc);
            AsT[kc+0][tok] = v.x; AsT[kc+1][tok] = v.y;
            AsT[kc+2][tok] = v.z; AsT[kc+3][tok] = v.w;
            int kr = idx >> 4, d = (idx & 15) * 4;
            *(float4*)&Bs[kr][d] = *(const float4*)(g_wkavg + (size_t)(k0 + kr) * DH + d);
        }
        __syncthreads();
#pragma unroll
        for (int k = 0; k < 32; k++) {
            float4 a = *(float4*)&AsT[k][ty*4];
            float4 b = *(float4*)&Bs[k][tx*4];
            float aa[4] = {a.x, a.y, a.z, a.w};
            float bb[4] = {b.x, b.y, b.z, b.w};
#pragma unroll
            for (int i = 0; i < 4; i++)
#pragma unroll
                for (int j = 0; j < 4; j++)
                    acc[i][j] = fmaf(aa[i], bb[j], acc[i][j]);
        }
    }
    float* dst = g_mpart + (size_t)blockIdx.y * NTOK * DH;
#pragma unroll
    for (int i = 0; i < 4; i++)
#pragma unroll
        for (int j = 0; j < 4; j++)
            dst[(size_t)(m0 + ty*4 + i) * DH + tx*4 + j] = acc[i][j];
}

// sum 8 partials (fixed order) + row-normalize -> g_nmet
__global__ __launch_bounds__(256) void metric_norm_kernel()
{
    int row = blockIdx.x * 8 + (threadIdx.x >> 5);
    int lane = threadIdx.x & 31;
    size_t off = (size_t)row * DH + lane*2;
    float2 v = *(float2*)&g_mpart[off];
#pragma unroll
    for (int p = 1; p < 8; p++) {
        float2 u = *(float2*)&g_mpart[(size_t)p * NTOK * DH + off];
        v.x += u.x; v.y += u.y;
    }
    float sq = v.x*v.x + v.y*v.y;
#pragma unroll
    for (int o = 16; o > 0; o >>= 1)
        sq += __shfl_xor_sync(0xffffffffu, sq, o);
    float nrm = sqrtf(sq);
    v.x /= nrm; v.y /= nrm;
    *(float2*)&g_nmet[off] = v;
}

// ---------------- tensor-core flash attention (128q x 64k, dh=64) ------------
// 256 threads / 8 warps; warp w owns q rows [w*16, w*16+16).
// Q/P A-fragments via ldmatrix.x4; K B-fragments via ldmatrix.x2; V stays LDS.
#define ATP 68   // K/Q/P pitch: rows 16B-aligned, 8-row phases bank-distinct
#define VTP 72   // V pitch (token-major)
#define AQ_WORDS (128*ATP)
#define AK_WORDS (64*ATP)
#define AV_WORDS (64*VTP)
#define ATTN_SMEM_B ((AQ_WORDS + 2*AK_WORDS + 2*AV_WORDS + 128*ATP) * 4 + 2*64*4)

__global__ __launch_bounds__(256) void attn_tc_kernel(
    const float* __restrict__ qkv, const float* __restrict__ sizev,
    float* __restrict__ xa)
{
    extern __shared__ uint32_t smu[];
    uint32_t* Qs = smu;                                   // [128][ATP] (scaled 0.125)
    uint32_t* Ks = smu + AQ_WORDS;                        // [2][64][ATP] token-major
    uint32_t* Vs = smu + AQ_WORDS + 2*AK_WORDS;           // [2][64][VTP] token-major
    uint32_t* Ps = smu + AQ_WORDS + 2*AK_WORDS + 2*AV_WORDS; // [128][ATP]
    float* logs  = (float*)(Ps + 128*ATP);                // [2][64]

    int tid  = threadIdx.x;
    int lane = tid & 31, w = tid >> 5;       // 8 warps
    int g = lane >> 2, qd = lane & 3;
    int h = blockIdx.y;
    int q0 = blockIdx.x * 128;
    int wq = w * 16;
    int qrow0 = (wq + g) * ATP, qrow1 = (wq + g + 8) * ATP;

    // ldmatrix lane components
    int lrow = ((lane >> 3) & 1) * 8 + (lane & 7);   // x4 row-within-16
    int lcol = (lane >> 4) * 4;                       // x4 col offset
    int krow = lane & 7;                              // x2 row-within-8
    int kcol = ((lane >> 3) & 1) * 4;                 // x2 col offset

    uint32_t qsBase = (uint32_t)__cvta_generic_to_shared(Qs);
    uint32_t ksBase = (uint32_t)__cvta_generic_to_shared(Ks);
    uint32_t vsBase = (uint32_t)__cvta_generic_to_shared(Vs);
    uint32_t psBase = (uint32_t)__cvta_generic_to_shared(Ps);
    uint32_t qLane = qsBase + (uint32_t)(((wq + lrow) * ATP + lcol) * 4);
    uint32_t pLane = psBase + (uint32_t)(((wq + lrow) * ATP + lcol) * 4);
    uint32_t kLane = (uint32_t)((krow * ATP + kcol) * 4);

    { // load Q tile (values tf32 already; fold 0.125 then re-round = exact)
        int tok = tid & 127, chunk = tid >> 7;
        const float* src = qkv + (size_t)(q0 + tok) * (3*CDIM) + h*DH + chunk*32;
#pragma unroll
        for (int f = 0; f < 8; f++) {
            float4 v = *(const float4*)(src + f*4);
            uint4 u;
            u.x = f2tf32(v.x * 0.125f); u.y = f2tf32(v.y * 0.125f);
            u.z = f2tf32(v.z * 0.125f); u.w = f2tf32(v.w * 0.125f);
            *(uint4*)&Qs[tok*ATP + chunk*32 + f*4] = u;
        }
    }

    auto issue_tile = [&](int kt) {
        int s = kt & 1;
        int k0 = kt * 64;
        int tok = tid & 63, quad = tid >> 6;
        const float* kbase = qkv + (size_t)(k0 + tok)*(3*CDIM) + CDIM + h*DH;
        const float* vbase = kbase + CDIM;
        uint32_t kdst = ksBase + (uint32_t)((s*AK_WORDS + tok*ATP)*4);
        uint32_t vdst = vsBase + (uint32_t)((s*AV_WORDS + tok*VTP)*4);
#pragma unroll
        for (int f = 0; f < 4; f++) {
            int d0 = quad*16 + f*4;
            cp_async16(kdst + d0*4, kbase + d0, 16);
            cp_async16(vdst + d0*4, vbase + d0, 16);
        }
        cp_commit();
        if (tid < 64) logs[s*64 + tid] = __logf(sizev[k0 + tid]);
    };

    float O[8][4];
#pragma unroll
    for (int dt = 0; dt < 8; dt++)
#pragma unroll
        for (int r = 0; r < 4; r++) O[dt][r] = 0.f;
    float rm0 = -3.0e38f, rm1 = -3.0e38f, rl0 = 0.f, rl1 = 0.f;

    issue_tile(0);

    for (int kt = 0; kt < NTOK/64; kt++) {
        cp_wait<0>();
        __syncthreads();
        if (kt + 1 < NTOK/64) issue_tile(kt + 1);

        uint32_t kStage = ksBase + (uint32_t)((kt & 1) * AK_WORDS * 4) + kLane;
        const uint32_t* Vb = Vs + (kt & 1) * AV_WORDS;
        const float*    lg = logs + (kt & 1) * 64;

        // ---- S = Q @ K^T ----
        float S[8][4];
#pragma unroll
        for (int nt = 0; nt < 8; nt++)
#pragma unroll
            for (int r = 0; r < 4; r++) S[nt][r] = 0.f;
#pragma unroll
        for (int kb = 0; kb < 8; kb++) {
            uint32_t a[4];
            ldsm_x4(a, qLane + (uint32_t)(kb*8*4));
#pragma unroll
            for (int nt = 0; nt < 8; nt++) {
                uint32_t b[2];
                ldsm_x2(b, kStage + (uint32_t)((nt*8*ATP + kb*8) * 4));
                mma_tf32(S[nt], a, b);
            }
        }

        // ---- register online softmax ----
        float m0 = -3.0e38f, m1 = -3.0e38f;
#pragma unroll
        for (int nt = 0; nt < 8; nt++) {
            float l0 = lg[nt*8 + 2*qd], l1 = lg[nt*8 + 2*qd + 1];
            S[nt][0] += l0; S[nt][1] += l1;
            S[nt][2] += l0; S[nt][3] += l1;
            m0 = fmaxf(m0, fmaxf(S[nt][0], S[nt][1]));
            m1 = fmaxf(m1, fmaxf(S[nt][2], S[nt][3]));
        }
#pragma unroll
        for (int off = 1; off < 4; off <<= 1) {
            m0 = fmaxf(m0, __shfl_xor_sync(0xffffffffu, m0, off));
            m1 = fmaxf(m1, __shfl_xor_sync(0xffffffffu, m1, off));
        }
        float n0 = fmaxf(rm0, m0), n1 = fmaxf(rm1, m1);
        float c0 = __expf(rm0 - n0), c1 = __expf(rm1 - n1);
        float s0 = 0.f, s1 = 0.f;
#pragma unroll
        for (int nt = 0; nt < 8; nt++) {
            S[nt][0] = __expf(S[nt][0] - n0);
            S[nt][1] = __expf(S[nt][1] - n0);
            S[nt][2] = __expf(S[nt][2] - n1);
            S[nt][3] = __expf(S[nt][3] - n1);
            s0 += S[nt][0] + S[nt][1];
            s1 += S[nt][2] + S[nt][3];
        }
#pragma unroll
        for (int off = 1; off < 4; off <<= 1) {
            s0 += __shfl_xor_sync(0xffffffffu, s0, off);
            s1 += __shfl_xor_sync(0xffffffffu, s1, off);
        }
        rl0 = rl0 * c0 + s0;  rl1 = rl1 * c1 + s1;
        rm0 = n0; rm1 = n1;
#pragma unroll
        for (int dt = 0; dt < 8; dt++) {
            O[dt][0] *= c0; O[dt][1] *= c0;
            O[dt][2] *= c1; O[dt][3] *= c1;
        }

        // stash P (tf32); consumed only by own warp -> syncwarp suffices
#pragma unroll
        for (int nt = 0; nt < 8; nt++) {
            uint2 u01, u23;
            u01.x = f2tf32(S[nt][0]); u01.y = f2tf32(S[nt][1]);
            u23.x = f2tf32(S[nt][2]); u23.y = f2tf32(S[nt][3]);
            *(uint2*)&Ps[qrow0 + nt*8 + 2*qd] = u01;
            *(uint2*)&Ps[qrow1 + nt*8 + 2*qd] = u23;
        }
        __syncwarp();

        // ---- O += P @ V ----
#pragma unroll
        for (int kb = 0; kb < 8; kb++) {
            uint32_t a[4];
            ldsm_x4(a, pLane + (uint32_t)(kb*8*4));
#pragma unroll
            for (int dt = 0; dt < 8; dt++) {
                uint32_t b[2];
                b[0] = Vb[(kb*8 + qd    )*VTP + dt*8 + g];
                b[1] = Vb[(kb*8 + qd + 4)*VTP + dt*8 + g];
                mma_tf32(O[dt], a, b);
            }
        }
    }

    // epilogue: write tf32-rounded xa (feeds proj GEMM)
    float i0 = 1.f / rl0, i1 = 1.f / rl1;
    int row0 = q0 + wq + g, row1 = row0 + 8;
#pragma unroll
    for (int dt = 0; dt < 8; dt++) {
        int col = h*DH + dt*8 + 2*qd;
        float2 o0; o0.x = rnd_tf32(O[dt][0]*i0); o0.y = rnd_tf32(O[dt][1]*i0);
        float2 o1; o1.x = rnd_tf32(O[dt][2]*i1); o1.y = rnd_tf32(O[dt][3]*i1);
        *(float2*)&xa[(size_t)row0 * CDIM + col] = o0;
        *(float2*)&xa[(size_t)row1 * CDIM + col] = o1;
    }
}

// ---------------- merge scoring: tiled max/argmax over dst -------------------
__global__ __launch_bounds__(256) void merge_score_kernel(const float* __restrict__ thr)
{
    __shared__ float dstm[64*65];
    int tid = threadIdx.x;
    int sl = tid >> 4;        // src local 0..15
    int tg = tid & 15;        // dst group
    int i  = blockIdx.x * 16 + sl;

    float sv[64];
    {
        const float4* sr = (const float4*)(g_nmet + (size_t)(2*i)*DH);
#pragma unroll
        for (int d4 = 0; d4 < 16; d4++) {
            float4 v = sr[d4];
            sv[d4*4+0] = v.x; sv[d4*4+1] = v.y;
            sv[d4*4+2] = v.z; sv[d4*4+3] = v.w;
        }
    }

    float best = -3.0e38f; int bestj = 0;
    for (int jt = 0; jt < NSRC/64; jt++) {
        __syncthreads();
        for (int u = 0; u < 4; u++) {
            int idx = u*256 + tid;
            int r = idx >> 4, dc = (idx & 15) * 4;
            const float4 v = *(const float4*)(g_nmet + (size_t)(2*(jt*64 + r) + 1)*DH + dc);
            float* dst = &dstm[r*65 + dc];
            dst[0] = v.x; dst[1] = v.y; dst[2] = v.z; dst[3] = v.w;
        }
        __syncthreads();
#pragma unroll
        for (int jj = 0; jj < 4; jj++) {
            int rloc = jj*16 + tg;
            const float* dv = &dstm[rloc*65];
            float dot = 0.f;
#pragma unroll
            for (int d = 0; d < 64; d++) dot = fmaf(sv[d], dv[d], dot);
            int j = jt*64 + rloc;
            if (dot > best || (dot == best && j < bestj)) { best = dot; bestj = j; }
        }
    }
#pragma unroll
    for (int off = 1; off < 16; off <<= 1) {
        float ov = __shfl_xor_sync(0xffffffffu, best, off);
        int   oj = __shfl_xor_sync(0xffffffffu, bestj, off);
        if (ov > best || (ov == best && oj < bestj)) { best = ov; bestj = oj; }
    }
    if (tg == 0) {
        if (i == 0) { g_mask[0] = 0; g_node[0] = 0; }   // row 0 forced -inf
        else { g_mask[i] = (best > thr[0]) ? 1 : 0; g_node[i] = bestj; }
    }
}

// ---------------- exclusive prefix scan of !mask -----------------------------
__global__ __launch_bounds__(1024) void scan_kernel()
{
    __shared__ int s[NSRC];
    int tid = threadIdx.x;
    int f = g_mask[tid] ? 0 : 1;
    s[tid] = f;
    __syncthreads();
    for (int off = 1; off < NSRC; off <<= 1) {
        int v = 0;
        if (tid >= off) v = s[tid - off];
        __syncthreads();
        s[tid] += v;
        __syncthreads();
    }
    g_pref[tid] = s[tid] - f;
    if (tid == NSRC-1) g_nUnm[0] = s[NSRC-1];
}

// ---------------- build unmerged rows ----------------------------------------
__global__ __launch_bounds__(256) void unm_kernel(const float* __restrict__ sizev)
{
    int i = blockIdx.x;
    if (g_mask[i]) return;
    int r = g_pref[i];
    float s = sizev[2*i];
    const float* xr = g_x1 + (size_t)(2*i) * CDIM;
    float* orow = g_outx + (size_t)r * CDIM;
    for (int c = threadIdx.x; c < CDIM; c += 256) orow[c] = xr[c] * s;
    if (threadIdx.x == 0) g_outs[r] = s;
}

// ---------------- build dst rows (deterministic gather of merges) ------------
__global__ __launch_bounds__(256) void dst_build_kernel(const float* __restrict__ sizev)
{
    __shared__ int smask[NSRC];
    __shared__ int snode[NSRC];
    int j = blockIdx.x, tid = threadIdx.x;
    for (int i = tid; i < NSRC; i += 256) {
        smask[i] = g_mask[i];
        snode[i] = g_node[i];
    }
    __syncthreads();

    int nU = g_nUnm[0];
    float s0 = sizev[2*j + 1];
    const float* dr = g_x1 + (size_t)(2*j + 1) * CDIM;
    float a0 = dr[tid]       * s0;
    float a1 = dr[tid + 256] * s0;
    float a2 = dr[tid + 512] * s0;
    float a3 = dr[tid + 768] * s0;
    float stot = s0;
    for (int i = 0; i < NSRC; i++) {
        if (smask[i] && snode[i] == j) {
            float si = sizev[2*i];
            const float* xr = g_x1 + (size_t)(2*i) * CDIM;
            a0 += xr[tid]       * si;
            a1 += xr[tid + 256] * si;
            a2 += xr[tid + 512] * si;
            a3 += xr[tid + 768] * si;
            stot += si;
        }
    }
    size_t r = (size_t)(nU + j) * CDIM;
    g_outx[r + tid]       = a0;
    g_outx[r + tid + 256] = a1;
    g_outx[r + tid + 512] = a2;
    g_outx[r + tid + 768] = a3;
    if (tid == 0) g_outs[nU + j] = stot;
}

// ---------------- size tail --------------------------------------------------
__global__ __launch_bounds__(256) void size_tail_kernel(float* __restrict__ out, int Nout)
{
    int i = blockIdx.x * 256 + threadIdx.x;
    if (i < Nout) out[(size_t)Nout * CDIM + i] = g_outs[i];
}

// ---------------- launcher ---------------------------------------------------
extern "C" void kernel_launch(void* const* d_in, const int* in_sizes, int n_in,
                              void* d_out, int out_size)
{
    const float* x      = (const float*)d_in[0];
    const float* sizev  = (const float*)d_in[1];
    const float* qkv_w  = (const float*)d_in[2];
    const float* proj_w = (const float*)d_in[3];
    const float* proj_b = (const float*)d_in[4];
    const float* ln1_g  = (const float*)d_in[5];
    const float* ln1_b  = (const float*)d_in[6];
    const float* ln2_g  = (const float*)d_in[7];
    const float* ln2_b  = (const float*)d_in[8];
    const float* fc1_w  = (const float*)d_in[9];
    const float* fc1_b  = (const float*)d_in[10];
    const float* fc2_w  = (const float*)d_in[11];
    const float* fc2_b  = (const float*)d_in[12];
    const float* thr    = (const float*)d_in[13];
    float* out = (float*)d_out;

    int Nout, packSize;
    if (out_size % (CDIM + 1) == 0) { Nout = out_size / (CDIM + 1); packSize = 1; }
    else                            { Nout = out_size / CDIM;       packSize = 0; }
    if (Nout > NTOK) Nout = NTOK;

    float *p_h, *p_hr, *p_qkv, *p_xa, *p_x1, *p_x2, *p_h2, *p_ff;
    float *p_wqkv, *p_wproj, *p_wfc1, *p_wfc2;
    cudaGetSymbolAddress((void**)&p_h,    g_h);
    cudaGetSymbolAddress((void**)&p_hr,   g_hr);
    cudaGetSymbolAddress((void**)&p_qkv,  g_qkv);
    cudaGetSymbolAddress((void**)&p_xa,   g_xa);
    cudaGetSymbolAddress((void**)&p_x1,   g_x1);
    cudaGetSymbolAddress((void**)&p_x2,   g_x2);
    cudaGetSymbolAddress((void**)&p_h2,   g_h2);
    cudaGetSymbolAddress((void**)&p_ff,   g_ff);
    cudaGetSymbolAddress((void**)&p_wqkv, g_wqkv);
    cudaGetSymbolAddress((void**)&p_wproj,g_wproj);
    cudaGetSymbolAddress((void**)&p_wfc1, g_wfc1);
    cudaGetSymbolAddress((void**)&p_wfc2, g_wfc2);

    cudaFuncSetAttribute(attn_tc_kernel, cudaFuncAttributeMaxDynamicSharedMemorySize, ATTN_SMEM_B);
    cudaFuncSetAttribute(gemm_tf32<0,1>, cudaFuncAttributeMaxDynamicSharedMemorySize, GEMM_SMEM);
    cudaFuncSetAttribute(gemm_tf32<2,1>, cudaFuncAttributeMaxDynamicSharedMemorySize, GEMM_SMEM);
    cudaFuncSetAttribute(gemm_tf32<3,0>, cudaFuncAttributeMaxDynamicSharedMemorySize, GEMM_SMEM);

    // 0. pre-round all four weight matrices (single fused launch)
    round4_kernel<<<(N4_ALL + 255)/256, 256>>>(qkv_w, proj_w, fc1_w, fc2_w);
    // 1. LN1: exact h (metric) + rounded hr (GEMM)
    ln_kernel<<<NTOK, 256>>>(x, ln1_g, ln1_b, p_h, p_hr, NTOK);
    // 2a. averaged K-weights (fp32 merge-metric firewall)
    wkavg_kernel<<<(CDIM*DH + 255)/256, 256>>>(qkv_w);
    // 2b. QKV = hr @ wqkv, output rounded to tf32
    gemm_tf32<0,1><<<dim3(3*CDIM/128, NTOK/128), 128, GEMM_SMEM>>>(
        p_hr, p_wqkv, nullptr, nullptr, p_qkv, NTOK, 3*CDIM, CDIM);
    // 3. metric = normalize(h @ wkavg)  (fp32 split-K x8, exact mask decisions)
    metric_gemm_kernel<<<dim3(NTOK/64, 8), 256>>>();
    metric_norm_kernel<<<NTOK/8, 256>>>();
    // 4. attention -> xa (rounded)  (tf32 TC, cp.async, 128q/CTA, ldmatrix)
    attn_tc_kernel<<<dim3(NTOK/128, HEADS), 256, ATTN_SMEM_B>>>(p_qkv, sizev, p_xa);
    // 5. x1 = x + xa @ wproj + proj_b  (tf32)
    gemm_tf32<3,0><<<dim3(CDIM/128, NTOK/128), 128, GEMM_SMEM>>>(
        p_xa, p_wproj, proj_b, x, p_x1, NTOK, CDIM, CDIM);
    // 6. merge scores (tiled)
    merge_score_kernel<<<NSRC/16, 256>>>(thr);
    // 7. prefix scan
    scan_kernel<<<1, 1024>>>();
    // 8. unmerged rows
    unm_kernel<<<NSRC, 256>>>(sizev);
    // 9. dst rows
    dst_build_kernel<<<NSRC, 256>>>(sizev);
    // 10+11. fused x2 = outx/size, LN2 -> rounded h2
    divln_kernel<<<Nout, 256>>>(ln2_g, ln2_b, Nout);
    // 12. ff = round(gelu(h2 @ wfc1 + fc1_b))  (tf32)
    gemm_tf32<2,1><<<dim3(FF/128, (Nout + 127)/128), 128, GEMM_SMEM>>>(
        p_h2, p_wfc1, fc1_b, nullptr, p_ff, Nout, FF, CDIM);
    // 13. out = x2 + ff @ wfc2 + fc2_b  (tf32, writes d_out directly)
    gemm_tf32<3,0><<<dim3(CDIM/128, (Nout + 127)/128), 128, GEMM_SMEM>>>(
        p_ff, p_wfc2, fc2_b, p_x2, out, Nout, CDIM, FF);
    // 14. append sizes
    if (packSize)
        size_tail_kernel<<<(Nout + 255)/256, 256>>>(out, Nout);
}

// round 15
// speedup vs baseline: 1.0107x; 1.0107x over previous
#include <cuda_runtime.h>
#include <math.h>
#include <stdint.h>

// Problem constants (fixed shapes from setup_inputs)
#define NTOK 2048
#define CDIM 1024
#define HEADS 16
#define DH 64
#define FF 4096
#define NSRC 1024   // NTOK/2

// ---------------- scratch (device globals; no allocation allowed) ------------
__device__ float g_h    [NTOK*CDIM];
__device__ float g_hr   [NTOK*CDIM];    // tf32-rounded h (GEMM input)
__device__ float g_qkv  [NTOK*3*CDIM];  // tf32-rounded (QKV GEMM RND=1)
__device__ float g_wkavg[CDIM*DH];
__device__ float g_mpart[8*NTOK*DH];
__device__ float g_nmet [NTOK*DH];
__device__ float g_xa   [NTOK*CDIM];    // rounded at attn epilogue
__device__ float g_x1   [NTOK*CDIM];
__device__ int   g_mask [NSRC];
__device__ int   g_node [NSRC];
__device__ int   g_pref [NSRC];
__device__ int   g_nUnm [1];
__device__ float g_outx [NTOK*CDIM];
__device__ float g_outs [NTOK];
__device__ float g_x2   [NTOK*CDIM];
__device__ float g_h2   [NTOK*CDIM];    // rounded at fused div+LN2
__device__ float g_ff   [NTOK*FF];      // rounded at fc1 epilogue
// tf32-rounded weight copies
__device__ float g_wqkv [CDIM*3*CDIM];
__device__ float g_wproj[CDIM*CDIM];
__device__ float g_wfc1 [CDIM*FF];
__device__ float g_wfc2 [FF*CDIM];

// ---------------- helpers ----------------------------------------------------
__device__ __forceinline__ uint32_t f2tf32(float v) {
    uint32_t r;
    asm("cvt.rna.tf32.f32 %0, %1;" : "=r"(r) : "f"(v));
    return r;
}
__device__ __forceinline__ float rnd_tf32(float v) {
    return __uint_as_float(f2tf32(v));
}

__device__ __forceinline__ void mma_tf32(float c[4], const uint32_t a[4],
                                         const uint32_t b[2]) {
    asm volatile(
        "mma.sync.aligned.m16n8k8.row.col.f32.tf32.tf32.f32 "
        "{%0,%1,%2,%3}, {%4,%5,%6,%7}, {%8,%9}, {%0,%1,%2,%3};\n"
        : "+f"(c[0]), "+f"(c[1]), "+f"(c[2]), "+f"(c[3])
        : "r"(a[0]), "r"(a[1]), "r"(a[2]), "r"(a[3]), "r"(b[0]), "r"(b[1]));
}

__device__ __forceinline__ void cp_async16(uint32_t dst, const void* src, int szbytes) {
    asm volatile("cp.async.cg.shared.global [%0], [%1], 16, %2;\n"
                 :: "r"(dst), "l"(src), "r"(szbytes));
}
__device__ __forceinline__ void cp_commit() {
    asm volatile("cp.async.commit_group;\n");
}
template <int N>
__device__ __forceinline__ void cp_wait() {
    asm volatile("cp.async.wait_group %0;\n" :: "n"(N));
}

__device__ __forceinline__ float gelu_exact(float v) {
    return 0.5f * v * (1.0f + erff(v * 0.70710678118654752440f));
}

// ---------------- fused tf32 pre-rounding of all four weight buffers ---------
#define N4_QKV (CDIM*3*CDIM/4)
#define N4_PRJ (CDIM*CDIM/4)
#define N4_FC1 (CDIM*FF/4)
#define N4_FC2 (FF*CDIM/4)
#define N4_ALL (N4_QKV + N4_PRJ + N4_FC1 + N4_FC2)

__global__ __launch_bounds__(256) void round4_kernel(
    const float* __restrict__ w0, const float* __restrict__ w1,
    const float* __restrict__ w2, const float* __restrict__ w3)
{
    int i = blockIdx.x * 256 + threadIdx.x;
    if (i >= N4_ALL) return;
    const float4* src; float4* dst; int off;
    if (i < N4_QKV) {
        src = (const float4*)w0; dst = (float4*)g_wqkv; off = i;
    } else if (i < N4_QKV + N4_PRJ) {
        src = (const float4*)w1; dst = (float4*)g_wproj; off = i - N4_QKV;
    } else if (i < N4_QKV + N4_PRJ + N4_FC1) {
        src = (const float4*)w2; dst = (float4*)g_wfc1; off = i - N4_QKV - N4_PRJ;
    } else {
        src = (const float4*)w3; dst = (float4*)g_wfc2; off = i - N4_QKV - N4_PRJ - N4_FC1;
    }
    float4 v = src[off];
    v.x = rnd_tf32(v.x); v.y = rnd_tf32(v.y);
    v.z = rnd_tf32(v.z); v.w = rnd_tf32(v.w);
    dst[off] = v;
}

// ---------------- layernorm (exact + rounded outputs) ------------------------
__global__ __launch_bounds__(256) void ln_kernel(
    const float* __restrict__ x, const float* __restrict__ g,
    const float* __restrict__ b, float* __restrict__ out,
    float* __restrict__ out_r, int M)
{
    int row = blockIdx.x;
    if (row >= M) return;
    const float* xr = x + (size_t)row * CDIM;
    int tid = threadIdx.x;
    float v[4];
    float s = 0.f, sq = 0.f;
#pragma unroll
    for (int t = 0; t < 4; t++) {
        float vv = xr[tid + t*256];
        v[t] = vv; s += vv; sq += vv*vv;
    }
    __shared__ float rs[256], rq[256];
    rs[tid] = s; rq[tid] = sq;
    __syncthreads();
    for (int off = 128; off > 0; off >>= 1) {
        if (tid < off) { rs[tid] += rs[tid+off]; rq[tid] += rq[tid+off]; }
        __syncthreads();
    }
    float mean = rs[0] * (1.f/CDIM);
    float var  = rq[0] * (1.f/CDIM) - mean*mean;
    float rstd = rsqrtf(var + 1e-5f);
#pragma unroll
    for (int t = 0; t < 4; t++) {
        int c = tid + t*256;
        float o = (v[t] - mean) * rstd * g[c] + b[c];
        if (out)   out  [(size_t)row * CDIM + c] = o;
        if (out_r) out_r[(size_t)row * CDIM + c] = rnd_tf32(o);
    }
}

// ---------------- fused x2 = outx/size, then LN2 -> rounded h2 ----------------
__global__ __launch_bounds__(256) void divln_kernel(
    const float* __restrict__ g, const float* __restrict__ b, int M)
{
    int row = blockIdx.x;
    if (row >= M) return;
    int tid = threadIdx.x;
    float sdiv = g_outs[row];
    float v[4];
    float s = 0.f, sq = 0.f;
#pragma unroll
    for (int t = 0; t < 4; t++) {
        float vv = g_outx[(size_t)row * CDIM + tid + t*256] / sdiv;
        v[t] = vv; s += vv; sq += vv*vv;
        g_x2[(size_t)row * CDIM + tid + t*256] = vv;
    }
    __shared__ float rs[256], rq[256];
    rs[tid] = s; rq[tid] = sq;
    __syncthreads();
    for (int off = 128; off > 0; off >>= 1) {
        if (tid < off) { rs[tid] += rs[tid+off]; rq[tid] += rq[tid+off]; }
        __syncthreads();
    }
    float mean = rs[0] * (1.f/CDIM);
    float var  = rq[0] * (1.f/CDIM) - mean*mean;
    float rstd = rsqrtf(var + 1e-5f);
#pragma unroll
    for (int t = 0; t < 4; t++) {
        int c = tid + t*256;
        float o = (v[t] - mean) * rstd * g[c] + b[c];
        g_h2[(size_t)row * CDIM + c] = rnd_tf32(o);
    }
}

// ---------------- TF32 tensor-core GEMM, cp.async 4-stage, 64x64 warp tiles --
// 128 threads = 4 warps in 2x2; scalar LDS fragment loads (measured faster
// than ldmatrix here). __launch_bounds__(128,3): 168 regs, 3 CTAs/SM; 4-stage
// smem = 75.8KB, 3x = 227.3KB fits the 228KB carveout.
#define GSTAGES 4
#define AS_WORDS (GSTAGES*128*20)
#define BS_WORDS (GSTAGES*16*136)
#define GEMM_SMEM ((AS_WORDS + BS_WORDS) * 4)

template <int EPI, int RND>
__global__ __launch_bounds__(128, 3) void gemm_tf32(
    const float* __restrict__ A, const float* __restrict__ B,
    const float* __restrict__ bias, const float* __restrict__ res,
    float* __restrict__ C, int M, int N, int K)
{
    extern __shared__ uint32_t gsm[];
    uint32_t* As = gsm;              // [s][128][20]
    uint32_t* Bs = gsm + AS_WORDS;   // [s][16][136]

    int tid  = threadIdx.x;
    int lane = tid & 31, wid = tid >> 5;   // 4 warps
    int wm = wid >> 1, wn = wid & 1;       // 2x2
    int g  = lane >> 2, qd = lane & 3;
    int m0 = blockIdx.y * 128, n0 = blockIdx.x * 128;

    float acc[4][8][4];
#pragma unroll
    for (int i = 0; i < 4; i++)
#pragma unroll
        for (int j = 0; j < 8; j++)
#pragma unroll
            for (int r = 0; r < 4; r++) acc[i][j][r] = 0.f;

    const int nT = K >> 4;

    int ar[4], ac[4], br[4], bc[4], aSz[4];
#pragma unroll
    for (int u = 0; u < 4; u++) {
        int idx = u*128 + tid;
        ar[u] = idx >> 2;  ac[u] = (idx & 3) * 4;
        br[u] = idx >> 5;  bc[u] = (idx & 31) * 4;
        aSz[u] = (m0 + ar[u] < M) ? 16 : 0;
    }
    uint32_t asBase = (uint32_t)__cvta_generic_to_shared(As);
    uint32_t bsBase = (uint32_t)__cvta_generic_to_shared(Bs);

#pragma unroll
    for (int t = 0; t < GSTAGES-1; t++) {
        int k0 = t * 16;
#pragma unroll
        for (int u = 0; u < 4; u++) {
            cp_async16(asBase + (uint32_t)(((t*128 + ar[u])*20 + ac[u]) * 4),
                       A + (size_t)(m0 + ar[u]) * K + k0 + ac[u], aSz[u]);
            cp_async16(bsBase + (uint32_t)(((t*16 + br[u])*136 + bc[u]) * 4),
                       B + (size_t)(k0 + br[u]) * N + n0 + bc[u], 16);
        }
        cp_commit();
    }

    for (int t = 0; t < nT; t++) {
        cp_wait<GSTAGES-2>();
        __syncthreads();

        int nxt = t + GSTAGES - 1;
        if (nxt < nT) {
            int s  = nxt % GSTAGES;
            int k0 = nxt * 16;
#pragma unroll
            for (int u = 0; u < 4; u++) {
                cp_async16(asBase + (uint32_t)(((s*128 + ar[u])*20 + ac[u]) * 4),
                           A + (size_t)(m0 + ar[u]) * K + k0 + ac[u], aSz[u]);
                cp_async16(bsBase + (uint32_t)(((s*16 + br[u])*136 + bc[u]) * 4),
                           B + (size_t)(k0 + br[u]) * N + n0 + bc[u], 16);
            }
        }
        cp_commit();

        const uint32_t* Ab = As + (t % GSTAGES) * 128 * 20;
        const uint32_t* Bb = Bs + (t % GSTAGES) * 16 * 136;
#pragma unroll
        for (int ks = 0; ks < 2; ks++) {
            int kb = ks * 8;
            uint32_t af[4][4], bf[8][2];
#pragma unroll
            for (int mf = 0; mf < 4; mf++) {
                int r = wm*64 + mf*16 + g;
                af[mf][0] = Ab[(r    )*20 + kb + qd];
                af[mf][1] = Ab[(r + 8)*20 + kb + qd];
                af[mf][2] = Ab[(r    )*20 + kb + qd + 4];
                af[mf][3] = Ab[(r + 8)*20 + kb + qd + 4];
            }
#pragma unroll
            for (int nf = 0; nf < 8; nf++) {
                int c = wn*64 + nf*8 + g;
                bf[nf][0] = Bb[(kb + qd    )*136 + c];
                bf[nf][1] = Bb[(kb + qd + 4)*136 + c];
            }
#pragma unroll
            for (int mf = 0; mf < 4; mf++)
#pragma unroll
                for (int nf = 0; nf < 8; nf++)
                    mma_tf32(acc[mf][nf], af[mf], bf[nf]);
        }
    }

#pragma unroll
    for (int mf = 0; mf < 4; mf++) {
        int rbase = m0 + wm*64 + mf*16 + g;
#pragma unroll
        for (int half = 0; half < 2; half++) {
            int row = rbase + half*8;
            if (row >= M) continue;
#pragma unroll
            for (int nf = 0; nf < 8; nf++) {
                int col = n0 + wn*64 + nf*8 + 2*qd;
                float v0 = acc[mf][nf][half*2 + 0];
                float v1 = acc[mf][nf][half*2 + 1];
                if (EPI >= 1) { v0 += bias[col]; v1 += bias[col+1]; }
                if (EPI == 2) { v0 = gelu_exact(v0); v1 = gelu_exact(v1); }
                if (EPI == 3) {
                    v0 += res[(size_t)row * N + col];
                    v1 += res[(size_t)row * N + col + 1];
                }
                if (RND) { v0 = rnd_tf32(v0); v1 = rnd_tf32(v1); }
                float2 o; o.x = v0; o.y = v1;
                *(float2*)(C + (size_t)row * N + col) = o;
            }
        }
    }
}

// ---------------- fp32 merge-metric path (exactness firewall) ----------------
__global__ __launch_bounds__(256) void wkavg_kernel(const float* __restrict__ qkv_w)
{
    int idx = blockIdx.x * 256 + threadIdx.x;
    if (idx >= CDIM*DH) return;
    int c = idx >> 6, d = idx & 63;
    const float* base = qkv_w + (size_t)c * (3*CDIM) + CDIM + d;
    float s = 0.f;
#pragma unroll
    for (int h = 0; h < HEADS; h++) s += base[h * DH];
    g_wkavg[idx] = s * (1.f / HEADS);
}

// partial metric = h @ wkavg over K chunk of 128  (split-K x8, fp32 SIMT)
__global__ __launch_bounds__(256) void metric_gemm_kernel()
{
    __shared__ float AsT[32][68];   // [k][tok]
    __shared__ float Bs [32][68];   // [k][d]
    int tid = threadIdx.x;
    int tx = tid & 15, ty = tid >> 4;
    int m0 = blockIdx.x * 64;
    int kb = blockIdx.y * 128;

    float acc[4][4];
#pragma unroll
    for (int i = 0; i < 4; i++)
#pragma unroll
        for (int j = 0; j < 4; j++) acc[i][j] = 0.f;

    for (int k0 = kb; k0 < kb + 128; k0 += 32) {
        __syncthreads();
#pragma unroll
        for (int u = 0; u < 2; u++) {
            int idx = tid*2 + u;
            int tok = idx >> 3, kc = (idx & 7) * 4;
            float4 v = *(const float4*)(g_h + (size_t)(m0 + tok) * CDIM + k0 + kc);
            AsT[kc+0][tok] = v.x; AsT[kc+1][tok] = v.y;
            AsT[kc+2][tok] = v.z; AsT[kc+3][tok] = v.w;
            int kr = idx >> 4, d = (idx & 15) * 4;
            *(float4*)&Bs[kr][d] = *(const float4*)(g_wkavg + (size_t)(k0 + kr) * DH + d);
        }
        __syncthreads();
#pragma unroll
        for (int k = 0; k < 32; k++) {
            float4 a = *(float4*)&AsT[k][ty*4];
            float4 b = *(float4*)&Bs[k][tx*4];
            float aa[4] = {a.x, a.y, a.z, a.w};
            float bb[4] = {b.x, b.y, b.z, b.w};
#pragma unroll
            for (int i = 0; i < 4; i++)
#pragma unroll
                for (int j = 0; j < 4; j++)
                    acc[i][j] = fmaf(aa[i], bb[j], acc[i][j]);
        }
    }
    float* dst = g_mpart + (size_t)blockIdx.y * NTOK * DH;
#pragma unroll
    for (int i = 0; i < 4; i++)
#pragma unroll
        for (int j = 0; j < 4; j++)
            dst[(size_t)(m0 + ty*4 + i) * DH + tx*4 + j] = acc[i][j];
}

// sum 8 partials (fixed order) + row-normalize -> g_nmet
__global__ __launch_bounds__(256) void metric_norm_kernel()
{
    int row = blockIdx.x * 8 + (threadIdx.x >> 5);
    int lane = threadIdx.x & 31;
    size_t off = (size_t)row * DH + lane*2;
    float2 v = *(float2*)&g_mpart[off];
#pragma unroll
    for (int p = 1; p < 8; p++) {
        float2 u = *(float2*)&g_mpart[(size_t)p * NTOK * DH + off];
        v.x += u.x; v.y += u.y;
    }
    float sq = v.x*v.x + v.y*v.y;
#pragma unroll
    for (int o = 16; o > 0; o >>= 1)
        sq += __shfl_xor_sync(0xffffffffu, sq, o);
    float nrm = sqrtf(sq);
    v.x /= nrm; v.y /= nrm;
    *(float2*)&g_nmet[off] = v;
}

// ---------------- tensor-core flash attention (128q x 64k, dh=64) ------------
// 256 threads / 8 warps; warp w owns q rows [w*16, w*16+16).  Scalar LDS
// fragment loads (R12 config — measured best).
#define ATP 68   // K/Q/P pitch: frag addr%32 = 4g+qd -> conflict-free
#define VTP 72   // V pitch (token-major): frag addr%32 = 8qd+g -> conflict-free
#define AQ_WORDS (128*ATP)
#define AK_WORDS (64*ATP)
#define AV_WORDS (64*VTP)
#define ATTN_SMEM_B ((AQ_WORDS + 2*AK_WORDS + 2*AV_WORDS + 128*ATP) * 4 + 2*64*4)

__global__ __launch_bounds__(256) void attn_tc_kernel(
    const float* __restrict__ qkv, const float* __restrict__ sizev,
    float* __restrict__ xa)
{
    extern __shared__ uint32_t smu[];
    uint32_t* Qs = smu;                                   // [128][ATP] (scaled 0.125)
    uint32_t* Ks = smu + AQ_WORDS;                        // [2][64][ATP] token-major
    uint32_t* Vs = smu + AQ_WORDS + 2*AK_WORDS;           // [2][64][VTP] token-major
    uint32_t* Ps = smu + AQ_WORDS + 2*AK_WORDS + 2*AV_WORDS; // [128][ATP]
    float* logs  = (float*)(Ps + 128*ATP);                // [2][64]

    int tid  = threadIdx.x;
    int lane = tid & 31, w = tid >> 5;       // 8 warps
    int g = lane >> 2, qd = lane & 3;
    int h = blockIdx.y;
    int q0 = blockIdx.x * 128;
    int wq = w * 16;
    int qrow0 = (wq + g) * ATP, qrow1 = (wq + g + 8) * ATP;

    uint32_t ksBase = (uint32_t)__cvta_generic_to_shared(Ks);
    uint32_t vsBase = (uint32_t)__cvta_generic_to_shared(Vs);

    { // load Q tile (values tf32 already; fold 0.125 then re-round = exact)
        int tok = tid & 127, chunk = tid >> 7;
        const float* src = qkv + (size_t)(q0 + tok) * (3*CDIM) + h*DH + chunk*32;
#pragma unroll
        for (int f = 0; f < 8; f++) {
            float4 v = *(const float4*)(src + f*4);
            uint4 u;
            u.x = f2tf32(v.x * 0.125f); u.y = f2tf32(v.y * 0.125f);
            u.z = f2tf32(v.z * 0.125f); u.w = f2tf32(v.w * 0.125f);
            *(uint4*)&Qs[tok*ATP + chunk*32 + f*4] = u;
        }
    }

    auto issue_tile = [&](int kt) {
        int s = kt & 1;
        int k0 = kt * 64;
        int tok = tid & 63, quad = tid >> 6;
        const float* kbase = qkv + (size_t)(k0 + tok)*(3*CDIM) + CDIM + h*DH;
        const float* vbase = kbase + CDIM;
        uint32_t kdst = ksBase + (uint32_t)((s*AK_WORDS + tok*ATP)*4);
        uint32_t vdst = vsBase + (uint32_t)((s*AV_WORDS + tok*VTP)*4);
#pragma unroll
        for (int f = 0; f < 4; f++) {
            int d0 = quad*16 + f*4;
            cp_async16(kdst + d0*4, kbase + d0, 16);
            cp_async16(vdst + d0*4, vbase + d0, 16);
        }
        cp_commit();
        if (tid < 64) logs[s*64 + tid] = __logf(sizev[k0 + tid]);
    };

    float O[8][4];
#pragma unroll
    for (int dt = 0; dt < 8; dt++)
#pragma unroll
        for (int r = 0; r < 4; r++) O[dt][r] = 0.f;
    float rm0 = -3.0e38f, rm1 = -3.0e38f, rl0 = 0.f, rl1 = 0.f;

    issue_tile(0);

    for (int kt = 0; kt < NTOK/64; kt++) {
        cp_wait<0>();
        __syncthreads();
        if (kt + 1 < NTOK/64) issue_tile(kt + 1);

        const uint32_t* Kb = Ks + (kt & 1) * AK_WORDS;
        const uint32_t* Vb = Vs + (kt & 1) * AV_WORDS;
        const float*    lg = logs + (kt & 1) * 64;

        // ---- S = Q @ K^T ----
        float S[8][4];
#pragma unroll
        for (int nt = 0; nt < 8; nt++)
#pragma unroll
            for (int r = 0; r < 4; r++) S[nt][r] = 0.f;
#pragma unroll
        for (int kb = 0; kb < 8; kb++) {
            uint32_t a[4];
            a[0] = Qs[qrow0 + kb*8 + qd];
            a[1] = Qs[qrow1 + kb*8 + qd];
            a[2] = Qs[qrow0 + kb*8 + qd + 4];
            a[3] = Qs[qrow1 + kb*8 + qd + 4];
#pragma unroll
            for (int nt = 0; nt < 8; nt++) {
                uint32_t b[2];
                b[0] = Kb[(nt*8 + g)*ATP + kb*8 + qd];
                b[1] = Kb[(nt*8 + g)*ATP + kb*8 + qd + 4];
                mma_tf32(S[nt], a, b);
            }
        }

        // ---- register online softmax ----
        float m0 = -3.0e38f, m1 = -3.0e38f;
#pragma unroll
        for (int nt = 0; nt < 8; nt++) {
            float l0 = lg[nt*8 + 2*qd], l1 = lg[nt*8 + 2*qd + 1];
            S[nt][0] += l0; S[nt][1] += l1;
            S[nt][2] += l0; S[nt][3] += l1;
            m0 = fmaxf(m0, fmaxf(S[nt][0], S[nt][1]));
            m1 = fmaxf(m1, fmaxf(S[nt][2], S[nt][3]));
        }
#pragma unroll
        for (int off = 1; off < 4; off <<= 1) {
            m0 = fmaxf(m0, __shfl_xor_sync(0xffffffffu, m0, off));
            m1 = fmaxf(m1, __shfl_xor_sync(0xffffffffu, m1, off));
        }
        float n0 = fmaxf(rm0, m0), n1 = fmaxf(rm1, m1);
        float c0 = __expf(rm0 - n0), c1 = __expf(rm1 - n1);
        float s0 = 0.f, s1 = 0.f;
#pragma unroll
        for (int nt = 0; nt < 8; nt++) {
            S[nt][0] = __expf(S[nt][0] - n0);
            S[nt][1] = __expf(S[nt][1] - n0);
            S[nt][2] = __expf(S[nt][2] - n1);
            S[nt][3] = __expf(S[nt][3] - n1);
            s0 += S[nt][0] + S[nt][1];
            s1 += S[nt][2] + S[nt][3];
        }
#pragma unroll
        for (int off = 1; off < 4; off <<= 1) {
            s0 += __shfl_xor_sync(0xffffffffu, s0, off);
            s1 += __shfl_xor_sync(0xffffffffu, s1, off);
        }
        rl0 = rl0 * c0 + s0;  rl1 = rl1 * c1 + s1;
        rm0 = n0; rm1 = n1;
#pragma unroll
        for (int dt = 0; dt < 8; dt++) {
            O[dt][0] *= c0; O[dt][1] *= c0;
            O[dt][2] *= c1; O[dt][3] *= c1;
        }

        // stash P (tf32); consumed only by own warp -> syncwarp suffices
#pragma unroll
        for (int nt = 0; nt < 8; nt++) {
            uint2 u01, u23;
            u01.x = f2tf32(S[nt][0]); u01.y = f2tf32(S[nt][1]);
            u23.x = f2tf32(S[nt][2]); u23.y = f2tf32(S[nt][3]);
            *(uint2*)&Ps[qrow0 + nt*8 + 2*qd] = u01;
            *(uint2*)&Ps[qrow1 + nt*8 + 2*qd] = u23;
        }
        __syncwarp();

        // ---- O += P @ V ----
#pragma unroll
        for (int kb = 0; kb < 8; kb++) {
            uint32_t a[4];
            a[0] = Ps[qrow0 + kb*8 + qd];
            a[1] = Ps[qrow1 + kb*8 + qd];
            a[2] = Ps[qrow0 + kb*8 + qd + 4];
            a[3] = Ps[qrow1 + kb*8 + qd + 4];
#pragma unroll
            for (int dt = 0; dt < 8; dt++) {
                uint32_t b[2];
                b[0] = Vb[(kb*8 + qd    )*VTP + dt*8 + g];
                b[1] = Vb[(kb*8 + qd + 4)*VTP + dt*8 + g];
                mma_tf32(O[dt], a, b);
            }
        }
    }

    // epilogue: write tf32-rounded xa (feeds proj GEMM)
    float i0 = 1.f / rl0, i1 = 1.f / rl1;
    int row0 = q0 + wq + g, row1 = row0 + 8;
#pragma unroll
    for (int dt = 0; dt < 8; dt++) {
        int col = h*DH + dt*8 + 2*qd;
        float2 o0; o0.x = rnd_tf32(O[dt][0]*i0); o0.y = rnd_tf32(O[dt][1]*i0);
        float2 o1; o1.x = rnd_tf32(O[dt][2]*i1); o1.y = rnd_tf32(O[dt][3]*i1);
        *(float2*)&xa[(size_t)row0 * CDIM + col] = o0;
        *(float2*)&xa[(size_t)row1 * CDIM + col] = o1;
    }
}

// ---------------- merge scoring: tiled max/argmax over dst -------------------
__global__ __launch_bounds__(256) void merge_score_kernel(const float* __restrict__ thr)
{
    __shared__ float dstm[64*65];
    int tid = threadIdx.x;
    int sl = tid >> 4;        // src local 0..15
    int tg = tid & 15;        // dst group
    int i  = blockIdx.x * 16 + sl;

    float sv[64];
    {
        const float4* sr = (const float4*)(g_nmet + (size_t)(2*i)*DH);
#pragma unroll
        for (int d4 = 0; d4 < 16; d4++) {
            float4 v = sr[d4];
            sv[d4*4+0] = v.x; sv[d4*4+1] = v.y;
            sv[d4*4+2] = v.z; sv[d4*4+3] = v.w;
        }
    }

    float best = -3.0e38f; int bestj = 0;
    for (int jt = 0; jt < NSRC/64; jt++) {
        __syncthreads();
        for (int u = 0; u < 4; u++) {
            int idx = u*256 + tid;
            int r = idx >> 4, dc = (idx & 15) * 4;
            const float4 v = *(const float4*)(g_nmet + (size_t)(2*(jt*64 + r) + 1)*DH + dc);
            float* dst = &dstm[r*65 + dc];
            dst[0] = v.x; dst[1] = v.y; dst[2] = v.z; dst[3] = v.w;
        }
        __syncthreads();
#pragma unroll
        for (int jj = 0; jj < 4; jj++) {
            int rloc = jj*16 + tg;
            const float* dv = &dstm[rloc*65];
            float dot = 0.f;
#pragma unroll
            for (int d = 0; d < 64; d++) dot = fmaf(sv[d], dv[d], dot);
            int j = jt*64 + rloc;
            if (dot > best || (dot == best && j < bestj)) { best = dot; bestj = j; }
        }
    }
#pragma unroll
    for (int off = 1; off < 16; off <<= 1) {
        float ov = __shfl_xor_sync(0xffffffffu, best, off);
        int   oj = __shfl_xor_sync(0xffffffffu, bestj, off);
        if (ov > best || (ov == best && oj < bestj)) { best = ov; bestj = oj; }
    }
    if (tg == 0) {
        if (i == 0) { g_mask[0] = 0; g_node[0] = 0; }   // row 0 forced -inf
        else { g_mask[i] = (best > thr[0]) ? 1 : 0; g_node[i] = bestj; }
    }
}

// ---------------- exclusive prefix scan of !mask -----------------------------
__global__ __launch_bounds__(1024) void scan_kernel()
{
    __shared__ int s[NSRC];
    int tid = threadIdx.x;
    int f = g_mask[tid] ? 0 : 1;
    s[tid] = f;
    __syncthreads();
    for (int off = 1; off < NSRC; off <<= 1) {
        int v = 0;
        if (tid >= off) v = s[tid - off];
        __syncthreads();
        s[tid] += v;
        __syncthreads();
    }
    g_pref[tid] = s[tid] - f;
    if (tid == NSRC-1) g_nUnm[0] = s[NSRC-1];
}

// ---------------- build unmerged rows ----------------------------------------
__global__ __launch_bounds__(256) void unm_kernel(const float* __restrict__ sizev)
{
    int i = blockIdx.x;
    if (g_mask[i]) return;
    int r = g_pref[i];
    float s = sizev[2*i];
    const float* xr = g_x1 + (size_t)(2*i) * CDIM;
    float* orow = g_outx + (size_t)r * CDIM;
    for (int c = threadIdx.x; c < CDIM; c += 256) orow[c] = xr[c] * s;
    if (threadIdx.x == 0) g_outs[r] = s;
}

// ---------------- build dst rows (deterministic gather of merges) ------------
__global__ __launch_bounds__(256) void dst_build_kernel(const float* __restrict__ sizev)
{
    __shared__ int   smask[NSRC];
    __shared__ int   snode[NSRC];
    __shared__ float ssize[NSRC];
    int j = blockIdx.x, tid = threadIdx.x;
    for (int i = tid; i < NSRC; i += 256) {
        smask[i] = g_mask[i];
        snode[i] = g_node[i];
        ssize[i] = sizev[2*i];
    }
    __syncthreads();

    int nU = g_nUnm[0];
    float s0 = sizev[2*j + 1];
    const float* dr = g_x1 + (size_t)(2*j + 1) * CDIM;
    float a0 = dr[tid]       * s0;
    float a1 = dr[tid + 256] * s0;
    float a2 = dr[tid + 512] * s0;
    float a3 = dr[tid + 768] * s0;
    float stot = s0;
    for (int i = 0; i < NSRC; i++) {
        if (smask[i] && snode[i] == j) {
            float si = ssize[i];
            const float* xr = g_x1 + (size_t)(2*i) * CDIM;
            a0 += xr[tid]       * si;
            a1 += xr[tid + 256] * si;
            a2 += xr[tid + 512] * si;
            a3 += xr[tid + 768] * si;
            stot += si;
        }
    }
    size_t r = (size_t)(nU + j) * CDIM;
    g_outx[r + tid]       = a0;
    g_outx[r + tid + 256] = a1;
    g_outx[r + tid + 512] = a2;
    g_outx[r + tid + 768] = a3;
    if (tid == 0) g_outs[nU + j] = stot;
}

// ---------------- size tail --------------------------------------------------
__global__ __launch_bounds__(256) void size_tail_kernel(float* __restrict__ out, int Nout)
{
    int i = blockIdx.x * 256 + threadIdx.x;
    if (i < Nout) out[(size_t)Nout * CDIM + i] = g_outs[i];
}

// ---------------- launcher ---------------------------------------------------
extern "C" void kernel_launch(void* const* d_in, const int* in_sizes, int n_in,
                              void* d_out, int out_size)
{
    const float* x      = (const float*)d_in[0];
    const float* sizev  = (const float*)d_in[1];
    const float* qkv_w  = (const float*)d_in[2];
    const float* proj_w = (const float*)d_in[3];
    const float* proj_b = (const float*)d_in[4];
    const float* ln1_g  = (const float*)d_in[5];
    const float* ln1_b  = (const float*)d_in[6];
    const float* ln2_g  = (const float*)d_in[7];
    const float* ln2_b  = (const float*)d_in[8];
    const float* fc1_w  = (const float*)d_in[9];
    const float* fc1_b  = (const float*)d_in[10];
    const float* fc2_w  = (const float*)d_in[11];
    const float* fc2_b  = (const float*)d_in[12];
    const float* thr    = (const float*)d_in[13];
    float* out = (float*)d_out;

    int Nout, packSize;
    if (out_size % (CDIM + 1) == 0) { Nout = out_size / (CDIM + 1); packSize = 1; }
    else                            { Nout = out_size / CDIM;       packSize = 0; }
    if (Nout > NTOK) Nout = NTOK;

    float *p_h, *p_hr, *p_qkv, *p_xa, *p_x1, *p_x2, *p_h2, *p_ff;
    float *p_wqkv, *p_wproj, *p_wfc1, *p_wfc2;
    cudaGetSymbolAddress((void**)&p_h,    g_h);
    cudaGetSymbolAddress((void**)&p_hr,   g_hr);
    cudaGetSymbolAddress((void**)&p_qkv,  g_qkv);
    cudaGetSymbolAddress((void**)&p_xa,   g_xa);
    cudaGetSymbolAddress((void**)&p_x1,   g_x1);
    cudaGetSymbolAddress((void**)&p_x2,   g_x2);
    cudaGetSymbolAddress((void**)&p_h2,   g_h2);
    cudaGetSymbolAddress((void**)&p_ff,   g_ff);
    cudaGetSymbolAddress((void**)&p_wqkv, g_wqkv);
    cudaGetSymbolAddress((void**)&p_wproj,g_wproj);
    cudaGetSymbolAddress((void**)&p_wfc1, g_wfc1);
    cudaGetSymbolAddress((void**)&p_wfc2, g_wfc2);

    cudaFuncSetAttribute(attn_tc_kernel, cudaFuncAttributeMaxDynamicSharedMemorySize, ATTN_SMEM_B);
    cudaFuncSetAttribute(gemm_tf32<0,1>, cudaFuncAttributeMaxDynamicSharedMemorySize, GEMM_SMEM);
    cudaFuncSetAttribute(gemm_tf32<2,1>, cudaFuncAttributeMaxDynamicSharedMemorySize, GEMM_SMEM);
    cudaFuncSetAttribute(gemm_tf32<3,0>, cudaFuncAttributeMaxDynamicSharedMemorySize, GEMM_SMEM);

    // 0. pre-round all four weight matrices (single fused launch)
    round4_kernel<<<(N4_ALL + 255)/256, 256>>>(qkv_w, proj_w, fc1_w, fc2_w);
    // 1. LN1: exact h (metric) + rounded hr (GEMM)
    ln_kernel<<<NTOK, 256>>>(x, ln1_g, ln1_b, p_h, p_hr, NTOK);
    // 2a. averaged K-weights (fp32 merge-metric firewall)
    wkavg_kernel<<<(CDIM*DH + 255)/256, 256>>>(qkv_w);
    // 2b. QKV = hr @ wqkv, output rounded to tf32
    gemm_tf32<0,1><<<dim3(3*CDIM/128, NTOK/128), 128, GEMM_SMEM>>>(
        p_hr, p_wqkv, nullptr, nullptr, p_qkv, NTOK, 3*CDIM, CDIM);
    // 3. metric = normalize(h @ wkavg)  (fp32 split-K x8, exact mask decisions)
    metric_gemm_kernel<<<dim3(NTOK/64, 8), 256>>>();
    metric_norm_kernel<<<NTOK/8, 256>>>();
    // 4. attention -> xa (rounded)  (tf32 TC, cp.async, 128q/CTA — R12 best)
    attn_tc_kernel<<<dim3(NTOK/128, HEADS), 256, ATTN_SMEM_B>>>(p_qkv, sizev, p_xa);
    // 5. x1 = x + xa @ wproj + proj_b  (tf32)
    gemm_tf32<3,0><<<dim3(CDIM/128, NTOK/128), 128, GEMM_SMEM>>>(
        p_xa, p_wproj, proj_b, x, p_x1, NTOK, CDIM, CDIM);
    // 6. merge scores (tiled)
    merge_score_kernel<<<NSRC/16, 256>>>(thr);
    // 7. prefix scan
    scan_kernel<<<1, 1024>>>();
    // 8. unmerged rows
    unm_kernel<<<NSRC, 256>>>(sizev);
    // 9. dst rows
    dst_build_kernel<<<NSRC, 256>>>(sizev);
    // 10+11. fused x2 = outx/size, LN2 -> rounded h2
    divln_kernel<<<Nout, 256>>>(ln2_g, ln2_b, Nout);
    // 12. ff = round(gelu(h2 @ wfc1 + fc1_b))  (tf32)
    gemm_tf32<2,1><<<dim3(FF/128, (Nout + 127)/128), 128, GEMM_SMEM>>>(
        p_h2, p_wfc1, fc1_b, nullptr, p_ff, Nout, FF, CDIM);
    // 13. out = x2 + ff @ wfc2 + fc2_b  (tf32, writes d_out directly)
    gemm_tf32<3,0><<<dim3(CDIM/128, (Nout + 127)/128), 128, GEMM_SMEM>>>(
        p_ff, p_wfc2, fc2_b, p_x2, out, Nout, CDIM, FF);
    // 14. append sizes
    if (packSize)
        size_tail_kernel<<<(Nout + 255)/256, 256>>>(out, Nout);
}

// round 16
// speedup vs baseline: 1.0656x; 1.0543x over previous
#include <cuda_runtime.h>
#include <math.h>
#include <stdint.h>

// Problem constants (fixed shapes from setup_inputs)
#define NTOK 2048
#define CDIM 1024
#define HEADS 16
#define DH 64
#define FF 4096
#define NSRC 1024   // NTOK/2

// ---------------- scratch (device globals; no allocation allowed) ------------
__device__ float g_h    [NTOK*CDIM];
__device__ float g_hr   [NTOK*CDIM];    // tf32-rounded h (GEMM input)
__device__ float g_qkv  [NTOK*3*CDIM];  // tf32-rounded (QKV GEMM RND=1)
__device__ float g_wkavg[CDIM*DH];
__device__ float g_mpart[8*NTOK*DH];
__device__ float g_nmet [NTOK*DH];
__device__ float g_xa   [NTOK*CDIM];    // rounded at attn epilogue
__device__ float g_x1   [NTOK*CDIM];
__device__ int   g_mask [NSRC];
__device__ int   g_node [NSRC];
__device__ int   g_pref [NSRC];
__device__ int   g_nUnm [1];
__device__ float g_outx [NTOK*CDIM];
__device__ float g_outs [NTOK];
__device__ float g_x2   [NTOK*CDIM];
__device__ float g_h2   [NTOK*CDIM];    // rounded at fused div+LN2
__device__ float g_ff   [NTOK*FF];      // rounded at fc1 epilogue
// tf32-rounded weight copies
__device__ float g_wqkv [CDIM*3*CDIM];
__device__ float g_wproj[CDIM*CDIM];
__device__ float g_wfc1 [CDIM*FF];
__device__ float g_wfc2 [FF*CDIM];

// ---------------- helpers ----------------------------------------------------
__device__ __forceinline__ uint32_t f2tf32(float v) {
    uint32_t r;
    asm("cvt.rna.tf32.f32 %0, %1;" : "=r"(r) : "f"(v));
    return r;
}
__device__ __forceinline__ float rnd_tf32(float v) {
    return __uint_as_float(f2tf32(v));
}

__device__ __forceinline__ void mma_tf32(float c[4], const uint32_t a[4],
                                         const uint32_t b[2]) {
    asm volatile(
        "mma.sync.aligned.m16n8k8.row.col.f32.tf32.tf32.f32 "
        "{%0,%1,%2,%3}, {%4,%5,%6,%7}, {%8,%9}, {%0,%1,%2,%3};\n"
        : "+f"(c[0]), "+f"(c[1]), "+f"(c[2]), "+f"(c[3])
        : "r"(a[0]), "r"(a[1]), "r"(a[2]), "r"(a[3]), "r"(b[0]), "r"(b[1]));
}

__device__ __forceinline__ void cp_async16(uint32_t dst, const void* src, int szbytes) {
    asm volatile("cp.async.cg.shared.global [%0], [%1], 16, %2;\n"
                 :: "r"(dst), "l"(src), "r"(szbytes));
}
__device__ __forceinline__ void cp_commit() {
    asm volatile("cp.async.commit_group;\n");
}
template <int N>
__device__ __forceinline__ void cp_wait() {
    asm volatile("cp.async.wait_group %0;\n" :: "n"(N));
}

__device__ __forceinline__ float gelu_exact(float v) {
    return 0.5f * v * (1.0f + erff(v * 0.70710678118654752440f));
}

// ---------------- fused tf32 pre-rounding of all four weight buffers ---------
#define N4_QKV (CDIM*3*CDIM/4)
#define N4_PRJ (CDIM*CDIM/4)
#define N4_FC1 (CDIM*FF/4)
#define N4_FC2 (FF*CDIM/4)
#define N4_ALL (N4_QKV + N4_PRJ + N4_FC1 + N4_FC2)

__global__ __launch_bounds__(256) void round4_kernel(
    const float* __restrict__ w0, const float* __restrict__ w1,
    const float* __restrict__ w2, const float* __restrict__ w3)
{
    int i = blockIdx.x * 256 + threadIdx.x;
    if (i >= N4_ALL) return;
    const float4* src; float4* dst; int off;
    if (i < N4_QKV) {
        src = (const float4*)w0; dst = (float4*)g_wqkv; off = i;
    } else if (i < N4_QKV + N4_PRJ) {
        src = (const float4*)w1; dst = (float4*)g_wproj; off = i - N4_QKV;
    } else if (i < N4_QKV + N4_PRJ + N4_FC1) {
        src = (const float4*)w2; dst = (float4*)g_wfc1; off = i - N4_QKV - N4_PRJ;
    } else {
        src = (const float4*)w3; dst = (float4*)g_wfc2; off = i - N4_QKV - N4_PRJ - N4_FC1;
    }
    float4 v = src[off];
    v.x = rnd_tf32(v.x); v.y = rnd_tf32(v.y);
    v.z = rnd_tf32(v.z); v.w = rnd_tf32(v.w);
    dst[off] = v;
}

// ---------------- layernorm (exact + rounded outputs) ------------------------
__global__ __launch_bounds__(256) void ln_kernel(
    const float* __restrict__ x, const float* __restrict__ g,
    const float* __restrict__ b, float* __restrict__ out,
    float* __restrict__ out_r, int M)
{
    int row = blockIdx.x;
    if (row >= M) return;
    const float* xr = x + (size_t)row * CDIM;
    int tid = threadIdx.x;
    float v[4];
    float s = 0.f, sq = 0.f;
#pragma unroll
    for (int t = 0; t < 4; t++) {
        float vv = xr[tid + t*256];
        v[t] = vv; s += vv; sq += vv*vv;
    }
    __shared__ float rs[256], rq[256];
    rs[tid] = s; rq[tid] = sq;
    __syncthreads();
    for (int off = 128; off > 0; off >>= 1) {
        if (tid < off) { rs[tid] += rs[tid+off]; rq[tid] += rq[tid+off]; }
        __syncthreads();
    }
    float mean = rs[0] * (1.f/CDIM);
    float var  = rq[0] * (1.f/CDIM) - mean*mean;
    float rstd = rsqrtf(var + 1e-5f);
#pragma unroll
    for (int t = 0; t < 4; t++) {
        int c = tid + t*256;
        float o = (v[t] - mean) * rstd * g[c] + b[c];
        if (out)   out  [(size_t)row * CDIM + c] = o;
        if (out_r) out_r[(size_t)row * CDIM + c] = rnd_tf32(o);
    }
}

// ---------------- fused x2 = outx/size, then LN2 -> rounded h2 ----------------
__global__ __launch_bounds__(256) void divln_kernel(
    const float* __restrict__ g, const float* __restrict__ b, int M)
{
    int row = blockIdx.x;
    if (row >= M) return;
    int tid = threadIdx.x;
    float sdiv = g_outs[row];
    float v[4];
    float s = 0.f, sq = 0.f;
#pragma unroll
    for (int t = 0; t < 4; t++) {
        float vv = g_outx[(size_t)row * CDIM + tid + t*256] / sdiv;
        v[t] = vv; s += vv; sq += vv*vv;
        g_x2[(size_t)row * CDIM + tid + t*256] = vv;
    }
    __shared__ float rs[256], rq[256];
    rs[tid] = s; rq[tid] = sq;
    __syncthreads();
    for (int off = 128; off > 0; off >>= 1) {
        if (tid < off) { rs[tid] += rs[tid+off]; rq[tid] += rq[tid+off]; }
        __syncthreads();
    }
    float mean = rs[0] * (1.f/CDIM);
    float var  = rq[0] * (1.f/CDIM) - mean*mean;
    float rstd = rsqrtf(var + 1e-5f);
#pragma unroll
    for (int t = 0; t < 4; t++) {
        int c = tid + t*256;
        float o = (v[t] - mean) * rstd * g[c] + b[c];
        g_h2[(size_t)row * CDIM + c] = rnd_tf32(o);
    }
}

// ---------------- TF32 tensor-core GEMM, cp.async 3-stage (R12 optimum) ------
#define GSTAGES 3
#define AS_WORDS (GSTAGES*128*20)
#define BS_WORDS (GSTAGES*16*136)
#define GEMM_SMEM ((AS_WORDS + BS_WORDS) * 4)

template <int EPI, int RND>
__global__ __launch_bounds__(128, 3) void gemm_tf32(
    const float* __restrict__ A, const float* __restrict__ B,
    const float* __restrict__ bias, const float* __restrict__ res,
    float* __restrict__ C, int M, int N, int K)
{
    extern __shared__ uint32_t gsm[];
    uint32_t* As = gsm;              // [s][128][20]
    uint32_t* Bs = gsm + AS_WORDS;   // [s][16][136]

    int tid  = threadIdx.x;
    int lane = tid & 31, wid = tid >> 5;   // 4 warps
    int wm = wid >> 1, wn = wid & 1;       // 2x2
    int g  = lane >> 2, qd = lane & 3;
    int m0 = blockIdx.y * 128, n0 = blockIdx.x * 128;

    float acc[4][8][4];
#pragma unroll
    for (int i = 0; i < 4; i++)
#pragma unroll
        for (int j = 0; j < 8; j++)
#pragma unroll
            for (int r = 0; r < 4; r++) acc[i][j][r] = 0.f;

    const int nT = K >> 4;

    int ar[4], ac[4], br[4], bc[4], aSz[4];
#pragma unroll
    for (int u = 0; u < 4; u++) {
        int idx = u*128 + tid;
        ar[u] = idx >> 2;  ac[u] = (idx & 3) * 4;
        br[u] = idx >> 5;  bc[u] = (idx & 31) * 4;
        aSz[u] = (m0 + ar[u] < M) ? 16 : 0;
    }
    uint32_t asBase = (uint32_t)__cvta_generic_to_shared(As);
    uint32_t bsBase = (uint32_t)__cvta_generic_to_shared(Bs);

#pragma unroll
    for (int t = 0; t < GSTAGES-1; t++) {
        int k0 = t * 16;
#pragma unroll
        for (int u = 0; u < 4; u++) {
            cp_async16(asBase + (uint32_t)(((t*128 + ar[u])*20 + ac[u]) * 4),
                       A + (size_t)(m0 + ar[u]) * K + k0 + ac[u], aSz[u]);
            cp_async16(bsBase + (uint32_t)(((t*16 + br[u])*136 + bc[u]) * 4),
                       B + (size_t)(k0 + br[u]) * N + n0 + bc[u], 16);
        }
        cp_commit();
    }

    for (int t = 0; t < nT; t++) {
        cp_wait<GSTAGES-2>();
        __syncthreads();

        int nxt = t + GSTAGES - 1;
        if (nxt < nT) {
            int s  = nxt % GSTAGES;
            int k0 = nxt * 16;
#pragma unroll
            for (int u = 0; u < 4; u++) {
                cp_async16(asBase + (uint32_t)(((s*128 + ar[u])*20 + ac[u]) * 4),
                           A + (size_t)(m0 + ar[u]) * K + k0 + ac[u], aSz[u]);
                cp_async16(bsBase + (uint32_t)(((s*16 + br[u])*136 + bc[u]) * 4),
                           B + (size_t)(k0 + br[u]) * N + n0 + bc[u], 16);
            }
        }
        cp_commit();

        const uint32_t* Ab = As + (t % GSTAGES) * 128 * 20;
        const uint32_t* Bb = Bs + (t % GSTAGES) * 16 * 136;
#pragma unroll
        for (int ks = 0; ks < 2; ks++) {
            int kb = ks * 8;
            uint32_t af[4][4], bf[8][2];
#pragma unroll
            for (int mf = 0; mf < 4; mf++) {
                int r = wm*64 + mf*16 + g;
                af[mf][0] = Ab[(r    )*20 + kb + qd];
                af[mf][1] = Ab[(r + 8)*20 + kb + qd];
                af[mf][2] = Ab[(r    )*20 + kb + qd + 4];
                af[mf][3] = Ab[(r + 8)*20 + kb + qd + 4];
            }
#pragma unroll
            for (int nf = 0; nf < 8; nf++) {
                int c = wn*64 + nf*8 + g;
                bf[nf][0] = Bb[(kb + qd    )*136 + c];
                bf[nf][1] = Bb[(kb + qd + 4)*136 + c];
            }
#pragma unroll
            for (int mf = 0; mf < 4; mf++)
#pragma unroll
                for (int nf = 0; nf < 8; nf++)
                    mma_tf32(acc[mf][nf], af[mf], bf[nf]);
        }
    }

#pragma unroll
    for (int mf = 0; mf < 4; mf++) {
        int rbase = m0 + wm*64 + mf*16 + g;
#pragma unroll
        for (int half = 0; half < 2; half++) {
            int row = rbase + half*8;
            if (row >= M) continue;
#pragma unroll
            for (int nf = 0; nf < 8; nf++) {
                int col = n0 + wn*64 + nf*8 + 2*qd;
                float v0 = acc[mf][nf][half*2 + 0];
                float v1 = acc[mf][nf][half*2 + 1];
                if (EPI >= 1) { v0 += bias[col]; v1 += bias[col+1]; }
                if (EPI == 2) { v0 = gelu_exact(v0); v1 = gelu_exact(v1); }
                if (EPI == 3) {
                    v0 += res[(size_t)row * N + col];
                    v1 += res[(size_t)row * N + col + 1];
                }
                if (RND) { v0 = rnd_tf32(v0); v1 = rnd_tf32(v1); }
                float2 o; o.x = v0; o.y = v1;
                *(float2*)(C + (size_t)row * N + col) = o;
            }
        }
    }
}

// ---------------- fp32 merge-metric path (exactness firewall) ----------------
__global__ __launch_bounds__(256) void wkavg_kernel(const float* __restrict__ qkv_w)
{
    int idx = blockIdx.x * 256 + threadIdx.x;
    if (idx >= CDIM*DH) return;
    int c = idx >> 6, d = idx & 63;
    const float* base = qkv_w + (size_t)c * (3*CDIM) + CDIM + d;
    float s = 0.f;
#pragma unroll
    for (int h = 0; h < HEADS; h++) s += base[h * DH];
    g_wkavg[idx] = s * (1.f / HEADS);
}

// partial metric = h @ wkavg over K chunk of 128  (split-K x8, fp32 SIMT)
__global__ __launch_bounds__(256) void metric_gemm_kernel()
{
    __shared__ float AsT[32][68];   // [k][tok]
    __shared__ float Bs [32][68];   // [k][d]
    int tid = threadIdx.x;
    int tx = tid & 15, ty = tid >> 4;
    int m0 = blockIdx.x * 64;
    int kb = blockIdx.y * 128;

    float acc[4][4];
#pragma unroll
    for (int i = 0; i < 4; i++)
#pragma unroll
        for (int j = 0; j < 4; j++) acc[i][j] = 0.f;

    for (int k0 = kb; k0 < kb + 128; k0 += 32) {
        __syncthreads();
#pragma unroll
        for (int u = 0; u < 2; u++) {
            int idx = tid*2 + u;
            int tok = idx >> 3, kc = (idx & 7) * 4;
            float4 v = *(const float4*)(g_h + (size_t)(m0 + tok) * CDIM + k0 + kc);
            AsT[kc+0][tok] = v.x; AsT[kc+1][tok] = v.y;
            AsT[kc+2][tok] = v.z; AsT[kc+3][tok] = v.w;
            int kr = idx >> 4, d = (idx & 15) * 4;
            *(float4*)&Bs[kr][d] = *(const float4*)(g_wkavg + (size_t)(k0 + kr) * DH + d);
        }
        __syncthreads();
#pragma unroll
        for (int k = 0; k < 32; k++) {
            float4 a = *(float4*)&AsT[k][ty*4];
            float4 b = *(float4*)&Bs[k][tx*4];
            float aa[4] = {a.x, a.y, a.z, a.w};
            float bb[4] = {b.x, b.y, b.z, b.w};
#pragma unroll
            for (int i = 0; i < 4; i++)
#pragma unroll
                for (int j = 0; j < 4; j++)
                    acc[i][j] = fmaf(aa[i], bb[j], acc[i][j]);
        }
    }
    float* dst = g_mpart + (size_t)blockIdx.y * NTOK * DH;
#pragma unroll
    for (int i = 0; i < 4; i++)
#pragma unroll
        for (int j = 0; j < 4; j++)
            dst[(size_t)(m0 + ty*4 + i) * DH + tx*4 + j] = acc[i][j];
}

// sum 8 partials (fixed order) + row-normalize -> g_nmet
__global__ __launch_bounds__(256) void metric_norm_kernel()
{
    int row = blockIdx.x * 8 + (threadIdx.x >> 5);
    int lane = threadIdx.x & 31;
    size_t off = (size_t)row * DH + lane*2;
    float2 v = *(float2*)&g_mpart[off];
#pragma unroll
    for (int p = 1; p < 8; p++) {
        float2 u = *(float2*)&g_mpart[(size_t)p * NTOK * DH + off];
        v.x += u.x; v.y += u.y;
    }
    float sq = v.x*v.x + v.y*v.y;
#pragma unroll
    for (int o = 16; o > 0; o >>= 1)
        sq += __shfl_xor_sync(0xffffffffu, sq, o);
    float nrm = sqrtf(sq);
    v.x /= nrm; v.y /= nrm;
    *(float2*)&g_nmet[off] = v;
}

// ---------------- tensor-core flash attention (128q x 64k, dh=64) ------------
// 256 threads / 8 warps. Q fragments hoisted to registers (loop-invariant);
// the Qs smem region is then reused for P, cutting smem 141.5->104.5KB ->
// 2 CTAs/SM -> single-wave grid (256 CTAs <= 296 slots).
#define ATP 68   // Q/P/K pitch: frag addr%32 = 4g+qd -> conflict-free
#define VTP 72   // V pitch (token-major): frag addr%32 = 8qd+g -> conflict-free
#define AQ_WORDS (128*ATP)
#define AK_WORDS (64*ATP)
#define AV_WORDS (64*VTP)
#define ATTN_SMEM_B ((AQ_WORDS + 2*AK_WORDS + 2*AV_WORDS) * 4 + 2*64*4)

__global__ __launch_bounds__(256, 2) void attn_tc_kernel(
    const float* __restrict__ qkv, const float* __restrict__ sizev,
    float* __restrict__ xa)
{
    extern __shared__ uint32_t smu[];
    uint32_t* QPs = smu;                                  // [128][ATP] Q staging, then P
    uint32_t* Ks  = smu + AQ_WORDS;                       // [2][64][ATP] token-major
    uint32_t* Vs  = smu + AQ_WORDS + 2*AK_WORDS;          // [2][64][VTP] token-major
    float* logs   = (float*)(Vs + 2*AV_WORDS);            // [2][64]

    int tid  = threadIdx.x;
    int lane = tid & 31, w = tid >> 5;       // 8 warps
    int g = lane >> 2, qd = lane & 3;
    int h = blockIdx.y;
    int q0 = blockIdx.x * 128;
    int wq = w * 16;
    int qrow0 = (wq + g) * ATP, qrow1 = (wq + g + 8) * ATP;

    uint32_t ksBase = (uint32_t)__cvta_generic_to_shared(Ks);
    uint32_t vsBase = (uint32_t)__cvta_generic_to_shared(Vs);

    { // stage Q tile (values tf32 already; fold 0.125 then re-round = exact)
        int tok = tid & 127, chunk = tid >> 7;
        const float* src = qkv + (size_t)(q0 + tok) * (3*CDIM) + h*DH + chunk*32;
#pragma unroll
        for (int f = 0; f < 8; f++) {
            float4 v = *(const float4*)(src + f*4);
            uint4 u;
            u.x = f2tf32(v.x * 0.125f); u.y = f2tf32(v.y * 0.125f);
            u.z = f2tf32(v.z * 0.125f); u.w = f2tf32(v.w * 0.125f);
            *(uint4*)&QPs[tok*ATP + chunk*32 + f*4] = u;
        }
    }

    auto issue_tile = [&](int kt) {
        int s = kt & 1;
        int k0 = kt * 64;
        int tok = tid & 63, quad = tid >> 6;
        const float* kbase = qkv + (size_t)(k0 + tok)*(3*CDIM) + CDIM + h*DH;
        const float* vbase = kbase + CDIM;
        uint32_t kdst = ksBase + (uint32_t)((s*AK_WORDS + tok*ATP)*4);
        uint32_t vdst = vsBase + (uint32_t)((s*AV_WORDS + tok*VTP)*4);
#pragma unroll
        for (int f = 0; f < 4; f++) {
            int d0 = quad*16 + f*4;
            cp_async16(kdst + d0*4, kbase + d0, 16);
            cp_async16(vdst + d0*4, vbase + d0, 16);
        }
        cp_commit();
        if (tid < 64) logs[s*64 + tid] = __logf(sizev[k0 + tid]);
    };

    issue_tile(0);
    __syncthreads();   // Q staging visible to own warp reads below

    // hoist loop-invariant Q fragments into registers; QPs becomes P scratch.
    // Each warp reads/writes only its own 16-row slab -> program order suffices.
    uint32_t qa[8][4];
#pragma unroll
    for (int kb = 0; kb < 8; kb++) {
        qa[kb][0] = QPs[qrow0 + kb*8 + qd];
        qa[kb][1] = QPs[qrow1 + kb*8 + qd];
        qa[kb][2] = QPs[qrow0 + kb*8 + qd + 4];
        qa[kb][3] = QPs[qrow1 + kb*8 + qd + 4];
    }

    float O[8][4];
#pragma unroll
    for (int dt = 0; dt < 8; dt++)
#pragma unroll
        for (int r = 0; r < 4; r++) O[dt][r] = 0.f;
    float rm0 = -3.0e38f, rm1 = -3.0e38f, rl0 = 0.f, rl1 = 0.f;

    for (int kt = 0; kt < NTOK/64; kt++) {
        cp_wait<0>();
        __syncthreads();
        if (kt + 1 < NTOK/64) issue_tile(kt + 1);

        const uint32_t* Kb = Ks + (kt & 1) * AK_WORDS;
        const uint32_t* Vb = Vs + (kt & 1) * AV_WORDS;
        const float*    lg = logs + (kt & 1) * 64;

        // ---- S = Q @ K^T ----
        float S[8][4];
#pragma unroll
        for (int nt = 0; nt < 8; nt++)
#pragma unroll
            for (int r = 0; r < 4; r++) S[nt][r] = 0.f;
#pragma unroll
        for (int kb = 0; kb < 8; kb++) {
#pragma unroll
            for (int nt = 0; nt < 8; nt++) {
                uint32_t b[2];
                b[0] = Kb[(nt*8 + g)*ATP + kb*8 + qd];
                b[1] = Kb[(nt*8 + g)*ATP + kb*8 + qd + 4];
                mma_tf32(S[nt], qa[kb], b);
            }
        }

        // ---- register online softmax ----
        float m0 = -3.0e38f, m1 = -3.0e38f;
#pragma unroll
        for (int nt = 0; nt < 8; nt++) {
            float l0 = lg[nt*8 + 2*qd], l1 = lg[nt*8 + 2*qd + 1];
            S[nt][0] += l0; S[nt][1] += l1;
            S[nt][2] += l0; S[nt][3] += l1;
            m0 = fmaxf(m0, fmaxf(S[nt][0], S[nt][1]));
            m1 = fmaxf(m1, fmaxf(S[nt][2], S[nt][3]));
        }
#pragma unroll
        for (int off = 1; off < 4; off <<= 1) {
            m0 = fmaxf(m0, __shfl_xor_sync(0xffffffffu, m0, off));
            m1 = fmaxf(m1, __shfl_xor_sync(0xffffffffu, m1, off));
        }
        float n0 = fmaxf(rm0, m0), n1 = fmaxf(rm1, m1);
        float c0 = __expf(rm0 - n0), c1 = __expf(rm1 - n1);
        float s0 = 0.f, s1 = 0.f;
#pragma unroll
        for (int nt = 0; nt < 8; nt++) {
            S[nt][0] = __expf(S[nt][0] - n0);
            S[nt][1] = __expf(S[nt][1] - n0);
            S[nt][2] = __expf(S[nt][2] - n1);
            S[nt][3] = __expf(S[nt][3] - n1);
            s0 += S[nt][0] + S[nt][1];
            s1 += S[nt][2] + S[nt][3];
        }
#pragma unroll
        for (int off = 1; off < 4; off <<= 1) {
            s0 += __shfl_xor_sync(0xffffffffu, s0, off);
            s1 += __shfl_xor_sync(0xffffffffu, s1, off);
        }
        rl0 = rl0 * c0 + s0;  rl1 = rl1 * c1 + s1;
        rm0 = n0; rm1 = n1;
#pragma unroll
        for (int dt = 0; dt < 8; dt++) {
            O[dt][0] *= c0; O[dt][1] *= c0;
            O[dt][2] *= c1; O[dt][3] *= c1;
        }

        // stash P (tf32) into reused Q region; own-warp rows only -> syncwarp
#pragma unroll
        for (int nt = 0; nt < 8; nt++) {
            uint2 u01, u23;
            u01.x = f2tf32(S[nt][0]); u01.y = f2tf32(S[nt][1]);
            u23.x = f2tf32(S[nt][2]); u23.y = f2tf32(S[nt][3]);
            *(uint2*)&QPs[qrow0 + nt*8 + 2*qd] = u01;
            *(uint2*)&QPs[qrow1 + nt*8 + 2*qd] = u23;
        }
        __syncwarp();

        // ---- O += P @ V ----
#pragma unroll
        for (int kb = 0; kb < 8; kb++) {
            uint32_t a[4];
            a[0] = QPs[qrow0 + kb*8 + qd];
            a[1] = QPs[qrow1 + kb*8 + qd];
            a[2] = QPs[qrow0 + kb*8 + qd + 4];
            a[3] = QPs[qrow1 + kb*8 + qd + 4];
#pragma unroll
            for (int dt = 0; dt < 8; dt++) {
                uint32_t b[2];
                b[0] = Vb[(kb*8 + qd    )*VTP + dt*8 + g];
                b[1] = Vb[(kb*8 + qd + 4)*VTP + dt*8 + g];
                mma_tf32(O[dt], a, b);
            }
        }
    }

    // epilogue: write tf32-rounded xa (feeds proj GEMM)
    float i0 = 1.f / rl0, i1 = 1.f / rl1;
    int row0 = q0 + wq + g, row1 = row0 + 8;
#pragma unroll
    for (int dt = 0; dt < 8; dt++) {
        int col = h*DH + dt*8 + 2*qd;
        float2 o0; o0.x = rnd_tf32(O[dt][0]*i0); o0.y = rnd_tf32(O[dt][1]*i0);
        float2 o1; o1.x = rnd_tf32(O[dt][2]*i1); o1.y = rnd_tf32(O[dt][3]*i1);
        *(float2*)&xa[(size_t)row0 * CDIM + col] = o0;
        *(float2*)&xa[(size_t)row1 * CDIM + col] = o1;
    }
}

// ---------------- merge scoring: tiled max/argmax over dst -------------------
__global__ __launch_bounds__(256) void merge_score_kernel(const float* __restrict__ thr)
{
    __shared__ float dstm[64*65];
    int tid = threadIdx.x;
    int sl = tid >> 4;        // src local 0..15
    int tg = tid & 15;        // dst group
    int i  = blockIdx.x * 16 + sl;

    float sv[64];
    {
        const float4* sr = (const float4*)(g_nmet + (size_t)(2*i)*DH);
#pragma unroll
        for (int d4 = 0; d4 < 16; d4++) {
            float4 v = sr[d4];
            sv[d4*4+0] = v.x; sv[d4*4+1] = v.y;
            sv[d4*4+2] = v.z; sv[d4*4+3] = v.w;
        }
    }

    float best = -3.0e38f; int bestj = 0;
    for (int jt = 0; jt < NSRC/64; jt++) {
        __syncthreads();
        for (int u = 0; u < 4; u++) {
            int idx = u*256 + tid;
            int r = idx >> 4, dc = (idx & 15) * 4;
            const float4 v = *(const float4*)(g_nmet + (size_t)(2*(jt*64 + r) + 1)*DH + dc);
            float* dst = &dstm[r*65 + dc];
            dst[0] = v.x; dst[1] = v.y; dst[2] = v.z; dst[3] = v.w;
        }
        __syncthreads();
#pragma unroll
        for (int jj = 0; jj < 4; jj++) {
            int rloc = jj*16 + tg;
            const float* dv = &dstm[rloc*65];
            float dot = 0.f;
#pragma unroll
            for (int d = 0; d < 64; d++) dot = fmaf(sv[d], dv[d], dot);
            int j = jt*64 + rloc;
            if (dot > best || (dot == best && j < bestj)) { best = dot; bestj = j; }
        }
    }
#pragma unroll
    for (int off = 1; off < 16; off <<= 1) {
        float ov = __shfl_xor_sync(0xffffffffu, best, off);
        int   oj = __shfl_xor_sync(0xffffffffu, bestj, off);
        if (ov > best || (ov == best && oj < bestj)) { best = ov; bestj = oj; }
    }
    if (tg == 0) {
        if (i == 0) { g_mask[0] = 0; g_node[0] = 0; }   // row 0 forced -inf
        else { g_mask[i] = (best > thr[0]) ? 1 : 0; g_node[i] = bestj; }
    }
}

// ---------------- exclusive prefix scan of !mask -----------------------------
__global__ __launch_bounds__(1024) void scan_kernel()
{
    __shared__ int s[NSRC];
    int tid = threadIdx.x;
    int f = g_mask[tid] ? 0 : 1;
    s[tid] = f;
    __syncthreads();
    for (int off = 1; off < NSRC; off <<= 1) {
        int v = 0;
        if (tid >= off) v = s[tid - off];
        __syncthreads();
        s[tid] += v;
        __syncthreads();
    }
    g_pref[tid] = s[tid] - f;
    if (tid == NSRC-1) g_nUnm[0] = s[NSRC-1];
}

// ---------------- build unmerged rows ----------------------------------------
__global__ __launch_bounds__(256) void unm_kernel(const float* __restrict__ sizev)
{
    int i = blockIdx.x;
    if (g_mask[i]) return;
    int r = g_pref[i];
    float s = sizev[2*i];
    const float* xr = g_x1 + (size_t)(2*i) * CDIM;
    float* orow = g_outx + (size_t)r * CDIM;
    for (int c = threadIdx.x; c < CDIM; c += 256) orow[c] = xr[c] * s;
    if (threadIdx.x == 0) g_outs[r] = s;
}

// ---------------- build dst rows (deterministic gather of merges) ------------
__global__ __launch_bounds__(256) void dst_build_kernel(const float* __restrict__ sizev)
{
    __shared__ int   smask[NSRC];
    __shared__ int   snode[NSRC];
    __shared__ float ssize[NSRC];
    int j = blockIdx.x, tid = threadIdx.x;
    for (int i = tid; i < NSRC; i += 256) {
        smask[i] = g_mask[i];
        snode[i] = g_node[i];
        ssize[i] = sizev[2*i];
    }
    __syncthreads();

    int nU = g_nUnm[0];
    float s0 = sizev[2*j + 1];
    const float* dr = g_x1 + (size_t)(2*j + 1) * CDIM;
    float a0 = dr[tid]       * s0;
    float a1 = dr[tid + 256] * s0;
    float a2 = dr[tid + 512] * s0;
    float a3 = dr[tid + 768] * s0;
    float stot = s0;
    for (int i = 0; i < NSRC; i++) {
        if (smask[i] && snode[i] == j) {
            float si = ssize[i];
            const float* xr = g_x1 + (size_t)(2*i) * CDIM;
            a0 += xr[tid]       * si;
            a1 += xr[tid + 256] * si;
            a2 += xr[tid + 512] * si;
            a3 += xr[tid + 768] * si;
            stot += si;
        }
    }
    size_t r = (size_t)(nU + j) * CDIM;
    g_outx[r + tid]       = a0;
    g_outx[r + tid + 256] = a1;
    g_outx[r + tid + 512] = a2;
    g_outx[r + tid + 768] = a3;
    if (tid == 0) g_outs[nU + j] = stot;
}

// ---------------- size tail --------------------------------------------------
__global__ __launch_bounds__(256) void size_tail_kernel(float* __restrict__ out, int Nout)
{
    int i = blockIdx.x * 256 + threadIdx.x;
    if (i < Nout) out[(size_t)Nout * CDIM + i] = g_outs[i];
}

// ---------------- launcher ---------------------------------------------------
extern "C" void kernel_launch(void* const* d_in, const int* in_sizes, int n_in,
                              void* d_out, int out_size)
{
    const float* x      = (const float*)d_in[0];
    const float* sizev  = (const float*)d_in[1];
    const float* qkv_w  = (const float*)d_in[2];
    const float* proj_w = (const float*)d_in[3];
    const float* proj_b = (const float*)d_in[4];
    const float* ln1_g  = (const float*)d_in[5];
    const float* ln1_b  = (const float*)d_in[6];
    const float* ln2_g  = (const float*)d_in[7];
    const float* ln2_b  = (const float*)d_in[8];
    const float* fc1_w  = (const float*)d_in[9];
    const float* fc1_b  = (const float*)d_in[10];
    const float* fc2_w  = (const float*)d_in[11];
    const float* fc2_b  = (const float*)d_in[12];
    const float* thr    = (const float*)d_in[13];
    float* out = (float*)d_out;

    int Nout, packSize;
    if (out_size % (CDIM + 1) == 0) { Nout = out_size / (CDIM + 1); packSize = 1; }
    else                            { Nout = out_size / CDIM;       packSize = 0; }
    if (Nout > NTOK) Nout = NTOK;

    float *p_h, *p_hr, *p_qkv, *p_xa, *p_x1, *p_x2, *p_h2, *p_ff;
    float *p_wqkv, *p_wproj, *p_wfc1, *p_wfc2;
    cudaGetSymbolAddress((void**)&p_h,    g_h);
    cudaGetSymbolAddress((void**)&p_hr,   g_hr);
    cudaGetSymbolAddress((void**)&p_qkv,  g_qkv);
    cudaGetSymbolAddress((void**)&p_xa,   g_xa);
    cudaGetSymbolAddress((void**)&p_x1,   g_x1);
    cudaGetSymbolAddress((void**)&p_x2,   g_x2);
    cudaGetSymbolAddress((void**)&p_h2,   g_h2);
    cudaGetSymbolAddress((void**)&p_ff,   g_ff);
    cudaGetSymbolAddress((void**)&p_wqkv, g_wqkv);
    cudaGetSymbolAddress((void**)&p_wproj,g_wproj);
    cudaGetSymbolAddress((void**)&p_wfc1, g_wfc1);
    cudaGetSymbolAddress((void**)&p_wfc2, g_wfc2);

    cudaFuncSetAttribute(attn_tc_kernel, cudaFuncAttributeMaxDynamicSharedMemorySize, ATTN_SMEM_B);
    cudaFuncSetAttribute(gemm_tf32<0,1>, cudaFuncAttributeMaxDynamicSharedMemorySize, GEMM_SMEM);
    cudaFuncSetAttribute(gemm_tf32<2,1>, cudaFuncAttributeMaxDynamicSharedMemorySize, GEMM_SMEM);
    cudaFuncSetAttribute(gemm_tf32<3,0>, cudaFuncAttributeMaxDynamicSharedMemorySize, GEMM_SMEM);

    // 0. pre-round all four weight matrices (single fused launch)
    round4_kernel<<<(N4_ALL + 255)/256, 256>>>(qkv_w, proj_w, fc1_w, fc2_w);
    // 1. LN1: exact h (metric) + rounded hr (GEMM)
    ln_kernel<<<NTOK, 256>>>(x, ln1_g, ln1_b, p_h, p_hr, NTOK);
    // 2a. averaged K-weights (fp32 merge-metric firewall)
    wkavg_kernel<<<(CDIM*DH + 255)/256, 256>>>(qkv_w);
    // 2b. QKV = hr @ wqkv, output rounded to tf32
    gemm_tf32<0,1><<<dim3(3*CDIM/128, NTOK/128), 128, GEMM_SMEM>>>(
        p_hr, p_wqkv, nullptr, nullptr, p_qkv, NTOK, 3*CDIM, CDIM);
    // 3. metric = normalize(h @ wkavg)  (fp32 split-K x8, exact mask decisions)
    metric_gemm_kernel<<<dim3(NTOK/64, 8), 256>>>();
    metric_norm_kernel<<<NTOK/8, 256>>>();
    // 4. attention -> xa (rounded)  (tf32 TC, 128q/CTA, Q-in-regs, 2 CTAs/SM)
    attn_tc_kernel<<<dim3(NTOK/128, HEADS), 256, ATTN_SMEM_B>>>(p_qkv, sizev, p_xa);
    // 5. x1 = x + xa @ wproj + proj_b  (tf32)
    gemm_tf32<3,0><<<dim3(CDIM/128, NTOK/128), 128, GEMM_SMEM>>>(
        p_xa, p_wproj, proj_b, x, p_x1, NTOK, CDIM, CDIM);
    // 6. merge scores (tiled)
    merge_score_kernel<<<NSRC/16, 256>>>(thr);
    // 7. prefix scan
    scan_kernel<<<1, 1024>>>();
    // 8. unmerged rows
    unm_kernel<<<NSRC, 256>>>(sizev);
    // 9. dst rows
    dst_build_kernel<<<NSRC, 256>>>(sizev);
    // 10+11. fused x2 = outx/size, LN2 -> rounded h2
    divln_kernel<<<Nout, 256>>>(ln2_g, ln2_b, Nout);
    // 12. ff = round(gelu(h2 @ wfc1 + fc1_b))  (tf32)
    gemm_tf32<2,1><<<dim3(FF/128, (Nout + 127)/128), 128, GEMM_SMEM>>>(
        p_h2, p_wfc1, fc1_b, nullptr, p_ff, Nout, FF, CDIM);
    // 13. out = x2 + ff @ wfc2 + fc2_b  (tf32, writes d_out directly)
    gemm_tf32<3,0><<<dim3(CDIM/128, (Nout + 127)/128), 128, GEMM_SMEM>>>(
        p_ff, p_wfc2, fc2_b, p_x2, out, Nout, CDIM, FF);
    // 14. append sizes
    if (packSize)
        size_tail_kernel<<<(Nout + 255)/256, 256>>>(out, Nout);
}

// round 17
// speedup vs baseline: 1.0690x; 1.0032x over previous
#include <cuda_runtime.h>
#include <math.h>
#include <stdint.h>

// Problem constants (fixed shapes from setup_inputs)
#define NTOK 2048
#define CDIM 1024
#define HEADS 16
#define DH 64
#define FF 4096
#define NSRC 1024   // NTOK/2

// ---------------- scratch (device globals; no allocation allowed) ------------
__device__ float g_h    [NTOK*CDIM];
__device__ float g_hr   [NTOK*CDIM];    // tf32-rounded h (GEMM input)
__device__ float g_qkv  [NTOK*3*CDIM];  // tf32-rounded (QKV GEMM RND=1)
__device__ float g_wkavg[CDIM*DH];
__device__ float g_mpart[8*NTOK*DH];
__device__ float g_nmet [NTOK*DH];
__device__ float g_logs [NTOK];         // log(size), computed once
__device__ float g_xa   [NTOK*CDIM];    // rounded at attn epilogue
__device__ float g_x1   [NTOK*CDIM];
__device__ int   g_mask [NSRC];
__device__ int   g_node [NSRC];
__device__ int   g_pref [NSRC];
__device__ int   g_nUnm [1];
__device__ float g_outx [NTOK*CDIM];
__device__ float g_outs [NTOK];
__device__ float g_x2   [NTOK*CDIM];
__device__ float g_h2   [NTOK*CDIM];    // rounded at fused div+LN2
__device__ float g_ff   [NTOK*FF];      // rounded at fc1 epilogue
// tf32-rounded weight copies
__device__ float g_wqkv [CDIM*3*CDIM];
__device__ float g_wproj[CDIM*CDIM];
__device__ float g_wfc1 [CDIM*FF];
__device__ float g_wfc2 [FF*CDIM];

// ---------------- helpers ----------------------------------------------------
__device__ __forceinline__ uint32_t f2tf32(float v) {
    uint32_t r;
    asm("cvt.rna.tf32.f32 %0, %1;" : "=r"(r) : "f"(v));
    return r;
}
__device__ __forceinline__ float rnd_tf32(float v) {
    return __uint_as_float(f2tf32(v));
}

__device__ __forceinline__ void mma_tf32(float c[4], const uint32_t a[4],
                                         const uint32_t b[2]) {
    asm volatile(
        "mma.sync.aligned.m16n8k8.row.col.f32.tf32.tf32.f32 "
        "{%0,%1,%2,%3}, {%4,%5,%6,%7}, {%8,%9}, {%0,%1,%2,%3};\n"
        : "+f"(c[0]), "+f"(c[1]), "+f"(c[2]), "+f"(c[3])
        : "r"(a[0]), "r"(a[1]), "r"(a[2]), "r"(a[3]), "r"(b[0]), "r"(b[1]));
}

__device__ __forceinline__ void cp_async16(uint32_t dst, const void* src, int szbytes) {
    asm volatile("cp.async.cg.shared.global [%0], [%1], 16, %2;\n"
                 :: "r"(dst), "l"(src), "r"(szbytes));
}
__device__ __forceinline__ void cp_commit() {
    asm volatile("cp.async.commit_group;\n");
}
template <int N>
__device__ __forceinline__ void cp_wait() {
    asm volatile("cp.async.wait_group %0;\n" :: "n"(N));
}

__device__ __forceinline__ float gelu_exact(float v) {
    return 0.5f * v * (1.0f + erff(v * 0.70710678118654752440f));
}

// ---------------- fused tf32 pre-rounding of all four weight buffers ---------
#define N4_QKV (CDIM*3*CDIM/4)
#define N4_PRJ (CDIM*CDIM/4)
#define N4_FC1 (CDIM*FF/4)
#define N4_FC2 (FF*CDIM/4)
#define N4_ALL (N4_QKV + N4_PRJ + N4_FC1 + N4_FC2)

__global__ __launch_bounds__(256) void round4_kernel(
    const float* __restrict__ w0, const float* __restrict__ w1,
    const float* __restrict__ w2, const float* __restrict__ w3)
{
    int i = blockIdx.x * 256 + threadIdx.x;
    if (i >= N4_ALL) return;
    const float4* src; float4* dst; int off;
    if (i < N4_QKV) {
        src = (const float4*)w0; dst = (float4*)g_wqkv; off = i;
    } else if (i < N4_QKV + N4_PRJ) {
        src = (const float4*)w1; dst = (float4*)g_wproj; off = i - N4_QKV;
    } else if (i < N4_QKV + N4_PRJ + N4_FC1) {
        src = (const float4*)w2; dst = (float4*)g_wfc1; off = i - N4_QKV - N4_PRJ;
    } else {
        src = (const float4*)w3; dst = (float4*)g_wfc2; off = i - N4_QKV - N4_PRJ - N4_FC1;
    }
    float4 v = src[off];
    v.x = rnd_tf32(v.x); v.y = rnd_tf32(v.y);
    v.z = rnd_tf32(v.z); v.w = rnd_tf32(v.w);
    dst[off] = v;
}

// ---------------- log(size) precompute ----------------------------------------
__global__ __launch_bounds__(256) void log_kernel(const float* __restrict__ sizev)
{
    int i = blockIdx.x * 256 + threadIdx.x;
    if (i < NTOK) g_logs[i] = __logf(sizev[i]);
}

// ---------------- layernorm (exact + rounded outputs) ------------------------
__global__ __launch_bounds__(256) void ln_kernel(
    const float* __restrict__ x, const float* __restrict__ g,
    const float* __restrict__ b, float* __restrict__ out,
    float* __restrict__ out_r, int M)
{
    int row = blockIdx.x;
    if (row >= M) return;
    const float* xr = x + (size_t)row * CDIM;
    int tid = threadIdx.x;
    float v[4];
    float s = 0.f, sq = 0.f;
#pragma unroll
    for (int t = 0; t < 4; t++) {
        float vv = xr[tid + t*256];
        v[t] = vv; s += vv; sq += vv*vv;
    }
    __shared__ float rs[256], rq[256];
    rs[tid] = s; rq[tid] = sq;
    __syncthreads();
    for (int off = 128; off > 0; off >>= 1) {
        if (tid < off) { rs[tid] += rs[tid+off]; rq[tid] += rq[tid+off]; }
        __syncthreads();
    }
    float mean = rs[0] * (1.f/CDIM);
    float var  = rq[0] * (1.f/CDIM) - mean*mean;
    float rstd = rsqrtf(var + 1e-5f);
#pragma unroll
    for (int t = 0; t < 4; t++) {
        int c = tid + t*256;
        float o = (v[t] - mean) * rstd * g[c] + b[c];
        if (out)   out  [(size_t)row * CDIM + c] = o;
        if (out_r) out_r[(size_t)row * CDIM + c] = rnd_tf32(o);
    }
}

// ---------------- fused x2 = outx/size, then LN2 -> rounded h2 ----------------
__global__ __launch_bounds__(256) void divln_kernel(
    const float* __restrict__ g, const float* __restrict__ b, int M)
{
    int row = blockIdx.x;
    if (row >= M) return;
    int tid = threadIdx.x;
    float sdiv = g_outs[row];
    float v[4];
    float s = 0.f, sq = 0.f;
#pragma unroll
    for (int t = 0; t < 4; t++) {
        float vv = g_outx[(size_t)row * CDIM + tid + t*256] / sdiv;
        v[t] = vv; s += vv; sq += vv*vv;
        g_x2[(size_t)row * CDIM + tid + t*256] = vv;
    }
    __shared__ float rs[256], rq[256];
    rs[tid] = s; rq[tid] = sq;
    __syncthreads();
    for (int off = 128; off > 0; off >>= 1) {
        if (tid < off) { rs[tid] += rs[tid+off]; rq[tid] += rq[tid+off]; }
        __syncthreads();
    }
    float mean = rs[0] * (1.f/CDIM);
    float var  = rq[0] * (1.f/CDIM) - mean*mean;
    float rstd = rsqrtf(var + 1e-5f);
#pragma unroll
    for (int t = 0; t < 4; t++) {
        int c = tid + t*256;
        float o = (v[t] - mean) * rstd * g[c] + b[c];
        g_h2[(size_t)row * CDIM + c] = rnd_tf32(o);
    }
}

// ---------------- TF32 tensor-core GEMM, cp.async 3-stage (R12 optimum) ------
#define GSTAGES 3
#define AS_WORDS (GSTAGES*128*20)
#define BS_WORDS (GSTAGES*16*136)
#define GEMM_SMEM ((AS_WORDS + BS_WORDS) * 4)

template <int EPI, int RND>
__global__ __launch_bounds__(128, 3) void gemm_tf32(
    const float* __restrict__ A, const float* __restrict__ B,
    const float* __restrict__ bias, const float* __restrict__ res,
    float* __restrict__ C, int M, int N, int K)
{
    extern __shared__ uint32_t gsm[];
    uint32_t* As = gsm;              // [s][128][20]
    uint32_t* Bs = gsm + AS_WORDS;   // [s][16][136]

    int tid  = threadIdx.x;
    int lane = tid & 31, wid = tid >> 5;   // 4 warps
    int wm = wid >> 1, wn = wid & 1;       // 2x2
    int g  = lane >> 2, qd = lane & 3;
    int m0 = blockIdx.y * 128, n0 = blockIdx.x * 128;

    float acc[4][8][4];
#pragma unroll
    for (int i = 0; i < 4; i++)
#pragma unroll
        for (int j = 0; j < 8; j++)
#pragma unroll
            for (int r = 0; r < 4; r++) acc[i][j][r] = 0.f;

    const int nT = K >> 4;

    int ar[4], ac[4], br[4], bc[4], aSz[4];
#pragma unroll
    for (int u = 0; u < 4; u++) {
        int idx = u*128 + tid;
        ar[u] = idx >> 2;  ac[u] = (idx & 3) * 4;
        br[u] = idx >> 5;  bc[u] = (idx & 31) * 4;
        aSz[u] = (m0 + ar[u] < M) ? 16 : 0;
    }
    uint32_t asBase = (uint32_t)__cvta_generic_to_shared(As);
    uint32_t bsBase = (uint32_t)__cvta_generic_to_shared(Bs);

#pragma unroll
    for (int t = 0; t < GSTAGES-1; t++) {
        int k0 = t * 16;
#pragma unroll
        for (int u = 0; u < 4; u++) {
            cp_async16(asBase + (uint32_t)(((t*128 + ar[u])*20 + ac[u]) * 4),
                       A + (size_t)(m0 + ar[u]) * K + k0 + ac[u], aSz[u]);
            cp_async16(bsBase + (uint32_t)(((t*16 + br[u])*136 + bc[u]) * 4),
                       B + (size_t)(k0 + br[u]) * N + n0 + bc[u], 16);
        }
        cp_commit();
    }

    for (int t = 0; t < nT; t++) {
        cp_wait<GSTAGES-2>();
        __syncthreads();

        int nxt = t + GSTAGES - 1;
        if (nxt < nT) {
            int s  = nxt % GSTAGES;
            int k0 = nxt * 16;
#pragma unroll
            for (int u = 0; u < 4; u++) {
                cp_async16(asBase + (uint32_t)(((s*128 + ar[u])*20 + ac[u]) * 4),
                           A + (size_t)(m0 + ar[u]) * K + k0 + ac[u], aSz[u]);
                cp_async16(bsBase + (uint32_t)(((s*16 + br[u])*136 + bc[u]) * 4),
                           B + (size_t)(k0 + br[u]) * N + n0 + bc[u], 16);
            }
        }
        cp_commit();

        const uint32_t* Ab = As + (t % GSTAGES) * 128 * 20;
        const uint32_t* Bb = Bs + (t % GSTAGES) * 16 * 136;
#pragma unroll
        for (int ks = 0; ks < 2; ks++) {
            int kb = ks * 8;
            uint32_t af[4][4], bf[8][2];
#pragma unroll
            for (int mf = 0; mf < 4; mf++) {
                int r = wm*64 + mf*16 + g;
                af[mf][0] = Ab[(r    )*20 + kb + qd];
                af[mf][1] = Ab[(r + 8)*20 + kb + qd];
                af[mf][2] = Ab[(r    )*20 + kb + qd + 4];
                af[mf][3] = Ab[(r + 8)*20 + kb + qd + 4];
            }
#pragma unroll
            for (int nf = 0; nf < 8; nf++) {
                int c = wn*64 + nf*8 + g;
                bf[nf][0] = Bb[(kb + qd    )*136 + c];
                bf[nf][1] = Bb[(kb + qd + 4)*136 + c];
            }
#pragma unroll
            for (int mf = 0; mf < 4; mf++)
#pragma unroll
                for (int nf = 0; nf < 8; nf++)
                    mma_tf32(acc[mf][nf], af[mf], bf[nf]);
        }
    }

#pragma unroll
    for (int mf = 0; mf < 4; mf++) {
        int rbase = m0 + wm*64 + mf*16 + g;
#pragma unroll
        for (int half = 0; half < 2; half++) {
            int row = rbase + half*8;
            if (row >= M) continue;
#pragma unroll
            for (int nf = 0; nf < 8; nf++) {
                int col = n0 + wn*64 + nf*8 + 2*qd;
                float v0 = acc[mf][nf][half*2 + 0];
                float v1 = acc[mf][nf][half*2 + 1];
                if (EPI >= 1) { v0 += bias[col]; v1 += bias[col+1]; }
                if (EPI == 2) { v0 = gelu_exact(v0); v1 = gelu_exact(v1); }
                if (EPI == 3) {
                    v0 += res[(size_t)row * N + col];
                    v1 += res[(size_t)row * N + col + 1];
                }
                if (RND) { v0 = rnd_tf32(v0); v1 = rnd_tf32(v1); }
                float2 o; o.x = v0; o.y = v1;
                *(float2*)(C + (size_t)row * N + col) = o;
            }
        }
    }
}

// ---------------- fp32 merge-metric path (exactness firewall) ----------------
__global__ __launch_bounds__(256) void wkavg_kernel(const float* __restrict__ qkv_w)
{
    int idx = blockIdx.x * 256 + threadIdx.x;
    if (idx >= CDIM*DH) return;
    int c = idx >> 6, d = idx & 63;
    const float* base = qkv_w + (size_t)c * (3*CDIM) + CDIM + d;
    float s = 0.f;
#pragma unroll
    for (int h = 0; h < HEADS; h++) s += base[h * DH];
    g_wkavg[idx] = s * (1.f / HEADS);
}

// partial metric = h @ wkavg over K chunk of 128  (split-K x8, fp32 SIMT)
__global__ __launch_bounds__(256) void metric_gemm_kernel()
{
    __shared__ float AsT[32][68];   // [k][tok]
    __shared__ float Bs [32][68];   // [k][d]
    int tid = threadIdx.x;
    int tx = tid & 15, ty = tid >> 4;
    int m0 = blockIdx.x * 64;
    int kb = blockIdx.y * 128;

    float acc[4][4];
#pragma unroll
    for (int i = 0; i < 4; i++)
#pragma unroll
        for (int j = 0; j < 4; j++) acc[i][j] = 0.f;

    for (int k0 = kb; k0 < kb + 128; k0 += 32) {
        __syncthreads();
#pragma unroll
        for (int u = 0; u < 2; u++) {
            int idx = tid*2 + u;
            int tok = idx >> 3, kc = (idx & 7) * 4;
            float4 v = *(const float4*)(g_h + (size_t)(m0 + tok) * CDIM + k0 + kc);
            AsT[kc+0][tok] = v.x; AsT[kc+1][tok] = v.y;
            AsT[kc+2][tok] = v.z; AsT[kc+3][tok] = v.w;
            int kr = idx >> 4, d = (idx & 15) * 4;
            *(float4*)&Bs[kr][d] = *(const float4*)(g_wkavg + (size_t)(k0 + kr) * DH + d);
        }
        __syncthreads();
#pragma unroll
        for (int k = 0; k < 32; k++) {
            float4 a = *(float4*)&AsT[k][ty*4];
            float4 b = *(float4*)&Bs[k][tx*4];
            float aa[4] = {a.x, a.y, a.z, a.w};
            float bb[4] = {b.x, b.y, b.z, b.w};
#pragma unroll
            for (int i = 0; i < 4; i++)
#pragma unroll
                for (int j = 0; j < 4; j++)
                    acc[i][j] = fmaf(aa[i], bb[j], acc[i][j]);
        }
    }
    float* dst = g_mpart + (size_t)blockIdx.y * NTOK * DH;
#pragma unroll
    for (int i = 0; i < 4; i++)
#pragma unroll
        for (int j = 0; j < 4; j++)
            dst[(size_t)(m0 + ty*4 + i) * DH + tx*4 + j] = acc[i][j];
}

// sum 8 partials (fixed order) + row-normalize -> g_nmet
__global__ __launch_bounds__(256) void metric_norm_kernel()
{
    int row = blockIdx.x * 8 + (threadIdx.x >> 5);
    int lane = threadIdx.x & 31;
    size_t off = (size_t)row * DH + lane*2;
    float2 v = *(float2*)&g_mpart[off];
#pragma unroll
    for (int p = 1; p < 8; p++) {
        float2 u = *(float2*)&g_mpart[(size_t)p * NTOK * DH + off];
        v.x += u.x; v.y += u.y;
    }
    float sq = v.x*v.x + v.y*v.y;
#pragma unroll
    for (int o = 16; o > 0; o >>= 1)
        sq += __shfl_xor_sync(0xffffffffu, sq, o);
    float nrm = sqrtf(sq);
    v.x /= nrm; v.y /= nrm;
    *(float2*)&g_nmet[off] = v;
}

// ---------------- tensor-core flash attention (128q x 64k, dh=64) ------------
// 256 threads / 8 warps; Q fragments in registers, Qs smem reused for P.
// 104.5KB smem -> 2 CTAs/SM, single-wave grid.
#define ATP 68   // Q/P/K pitch: frag addr%32 = 4g+qd -> conflict-free
#define VTP 72   // V pitch (token-major): frag addr%32 = 8qd+g -> conflict-free
#define AQ_WORDS (128*ATP)
#define AK_WORDS (64*ATP)
#define AV_WORDS (64*VTP)
#define ATTN_SMEM_B ((AQ_WORDS + 2*AK_WORDS + 2*AV_WORDS) * 4 + 2*64*4)

__global__ __launch_bounds__(256, 2) void attn_tc_kernel(
    const float* __restrict__ qkv, float* __restrict__ xa)
{
    extern __shared__ uint32_t smu[];
    uint32_t* QPs = smu;                                  // [128][ATP] Q staging, then P
    uint32_t* Ks  = smu + AQ_WORDS;                       // [2][64][ATP] token-major
    uint32_t* Vs  = smu + AQ_WORDS + 2*AK_WORDS;          // [2][64][VTP] token-major
    float* logs   = (float*)(Vs + 2*AV_WORDS);            // [2][64]

    int tid  = threadIdx.x;
    int lane = tid & 31, w = tid >> 5;       // 8 warps
    int g = lane >> 2, qd = lane & 3;
    int h = blockIdx.y;
    int q0 = blockIdx.x * 128;
    int wq = w * 16;
    int qrow0 = (wq + g) * ATP, qrow1 = (wq + g + 8) * ATP;

    uint32_t ksBase = (uint32_t)__cvta_generic_to_shared(Ks);
    uint32_t vsBase = (uint32_t)__cvta_generic_to_shared(Vs);

    { // stage Q tile (values tf32 already; fold 0.125 then re-round = exact)
        int tok = tid & 127, chunk = tid >> 7;
        const float* src = qkv + (size_t)(q0 + tok) * (3*CDIM) + h*DH + chunk*32;
#pragma unroll
        for (int f = 0; f < 8; f++) {
            float4 v = *(const float4*)(src + f*4);
            uint4 u;
            u.x = f2tf32(v.x * 0.125f); u.y = f2tf32(v.y * 0.125f);
            u.z = f2tf32(v.z * 0.125f); u.w = f2tf32(v.w * 0.125f);
            *(uint4*)&QPs[tok*ATP + chunk*32 + f*4] = u;
        }
    }

    auto issue_tile = [&](int kt) {
        int s = kt & 1;
        int k0 = kt * 64;
        int tok = tid & 63, quad = tid >> 6;
        const float* kbase = qkv + (size_t)(k0 + tok)*(3*CDIM) + CDIM + h*DH;
        const float* vbase = kbase + CDIM;
        uint32_t kdst = ksBase + (uint32_t)((s*AK_WORDS + tok*ATP)*4);
        uint32_t vdst = vsBase + (uint32_t)((s*AV_WORDS + tok*VTP)*4);
#pragma unroll
        for (int f = 0; f < 4; f++) {
            int d0 = quad*16 + f*4;
            cp_async16(kdst + d0*4, kbase + d0, 16);
            cp_async16(vdst + d0*4, vbase + d0, 16);
        }
        cp_commit();
        if (tid < 64) logs[s*64 + tid] = g_logs[k0 + tid];
    };

    issue_tile(0);
    __syncthreads();   // Q staging visible

    // hoist loop-invariant Q fragments into registers; QPs becomes P scratch.
    uint32_t qa[8][4];
#pragma unroll
    for (int kb = 0; kb < 8; kb++) {
        qa[kb][0] = QPs[qrow0 + kb*8 + qd];
        qa[kb][1] = QPs[qrow1 + kb*8 + qd];
        qa[kb][2] = QPs[qrow0 + kb*8 + qd + 4];
        qa[kb][3] = QPs[qrow1 + kb*8 + qd + 4];
    }

    float O[8][4];
#pragma unroll
    for (int dt = 0; dt < 8; dt++)
#pragma unroll
        for (int r = 0; r < 4; r++) O[dt][r] = 0.f;
    float rm0 = -3.0e38f, rm1 = -3.0e38f, rl0 = 0.f, rl1 = 0.f;

    for (int kt = 0; kt < NTOK/64; kt++) {
        cp_wait<0>();
        __syncthreads();
        if (kt + 1 < NTOK/64) issue_tile(kt + 1);

        const uint32_t* Kb = Ks + (kt & 1) * AK_WORDS;
        const uint32_t* Vb = Vs + (kt & 1) * AV_WORDS;
        const float*    lg = logs + (kt & 1) * 64;

        // ---- S = Q @ K^T ----
        float S[8][4];
#pragma unroll
        for (int nt = 0; nt < 8; nt++)
#pragma unroll
            for (int r = 0; r < 4; r++) S[nt][r] = 0.f;
#pragma unroll
        for (int kb = 0; kb < 8; kb++) {
#pragma unroll
            for (int nt = 0; nt < 8; nt++) {
                uint32_t b[2];
                b[0] = Kb[(nt*8 + g)*ATP + kb*8 + qd];
                b[1] = Kb[(nt*8 + g)*ATP + kb*8 + qd + 4];
                mma_tf32(S[nt], qa[kb], b);
            }
        }

        // ---- register online softmax ----
        float m0 = -3.0e38f, m1 = -3.0e38f;
#pragma unroll
        for (int nt = 0; nt < 8; nt++) {
            float l0 = lg[nt*8 + 2*qd], l1 = lg[nt*8 + 2*qd + 1];
            S[nt][0] += l0; S[nt][1] += l1;
            S[nt][2] += l0; S[nt][3] += l1;
            m0 = fmaxf(m0, fmaxf(S[nt][0], S[nt][1]));
            m1 = fmaxf(m1, fmaxf(S[nt][2], S[nt][3]));
        }
#pragma unroll
        for (int off = 1; off < 4; off <<= 1) {
            m0 = fmaxf(m0, __shfl_xor_sync(0xffffffffu, m0, off));
            m1 = fmaxf(m1, __shfl_xor_sync(0xffffffffu, m1, off));
        }
        float n0 = fmaxf(rm0, m0), n1 = fmaxf(rm1, m1);
        float c0 = __expf(rm0 - n0), c1 = __expf(rm1 - n1);
        float s0 = 0.f, s1 = 0.f;
#pragma unroll
        for (int nt = 0; nt < 8; nt++) {
            S[nt][0] = __expf(S[nt][0] - n0);
            S[nt][1] = __expf(S[nt][1] - n0);
            S[nt][2] = __expf(S[nt][2] - n1);
            S[nt][3] = __expf(S[nt][3] - n1);
            s0 += S[nt][0] + S[nt][1];
            s1 += S[nt][2] + S[nt][3];
        }
#pragma unroll
        for (int off = 1; off < 4; off <<= 1) {
            s0 += __shfl_xor_sync(0xffffffffu, s0, off);
            s1 += __shfl_xor_sync(0xffffffffu, s1, off);
        }
        rl0 = rl0 * c0 + s0;  rl1 = rl1 * c1 + s1;
        rm0 = n0; rm1 = n1;
#pragma unroll
        for (int dt = 0; dt < 8; dt++) {
            O[dt][0] *= c0; O[dt][1] *= c0;
            O[dt][2] *= c1; O[dt][3] *= c1;
        }

        // stash P (tf32) into reused Q region; own-warp rows only -> syncwarp
#pragma unroll
        for (int nt = 0; nt < 8; nt++) {
            uint2 u01, u23;
            u01.x = f2tf32(S[nt][0]); u01.y = f2tf32(S[nt][1]);
            u23.x = f2tf32(S[nt][2]); u23.y = f2tf32(S[nt][3]);
            *(uint2*)&QPs[qrow0 + nt*8 + 2*qd] = u01;
            *(uint2*)&QPs[qrow1 + nt*8 + 2*qd] = u23;
        }
        __syncwarp();

        // ---- O += P @ V ----
#pragma unroll
        for (int kb = 0; kb < 8; kb++) {
            uint32_t a[4];
            a[0] = QPs[qrow0 + kb*8 + qd];
            a[1] = QPs[qrow1 + kb*8 + qd];
            a[2] = QPs[qrow0 + kb*8 + qd + 4];
            a[3] = QPs[qrow1 + kb*8 + qd + 4];
#pragma unroll
            for (int dt = 0; dt < 8; dt++) {
                uint32_t b[2];
                b[0] = Vb[(kb*8 + qd    )*VTP + dt*8 + g];
                b[1] = Vb[(kb*8 + qd + 4)*VTP + dt*8 + g];
                mma_tf32(O[dt], a, b);
            }
        }
    }

    // epilogue: write tf32-rounded xa (feeds proj GEMM)
    float i0 = 1.f / rl0, i1 = 1.f / rl1;
    int row0 = q0 + wq + g, row1 = row0 + 8;
#pragma unroll
    for (int dt = 0; dt < 8; dt++) {
        int col = h*DH + dt*8 + 2*qd;
        float2 o0; o0.x = rnd_tf32(O[dt][0]*i0); o0.y = rnd_tf32(O[dt][1]*i0);
        float2 o1; o1.x = rnd_tf32(O[dt][2]*i1); o1.y = rnd_tf32(O[dt][3]*i1);
        *(float2*)&xa[(size_t)row0 * CDIM + col] = o0;
        *(float2*)&xa[(size_t)row1 * CDIM + col] = o1;
    }
}

// ---------------- merge scoring: 128 blocks, warp-per-src --------------------
__global__ __launch_bounds__(256) void merge_score_kernel(const float* __restrict__ thr)
{
    __shared__ float dstm[64*65];
    int tid = threadIdx.x;
    int sl = tid >> 5;        // src local 0..7  (one warp per src)
    int tg = tid & 31;        // dst group lane
    int i  = blockIdx.x * 8 + sl;

    float sv[64];
    {
        const float4* sr = (const float4*)(g_nmet + (size_t)(2*i)*DH);
#pragma unroll
        for (int d4 = 0; d4 < 16; d4++) {
            float4 v = sr[d4];
            sv[d4*4+0] = v.x; sv[d4*4+1] = v.y;
            sv[d4*4+2] = v.z; sv[d4*4+3] = v.w;
        }
    }

    float best = -3.0e38f; int bestj = 0;
    for (int jt = 0; jt < NSRC/64; jt++) {
        __syncthreads();
        for (int u = 0; u < 4; u++) {
            int idx = u*256 + tid;
            int r = idx >> 4, dc = (idx & 15) * 4;
            const float4 v = *(const float4*)(g_nmet + (size_t)(2*(jt*64 + r) + 1)*DH + dc);
            float* dst = &dstm[r*65 + dc];
            dst[0] = v.x; dst[1] = v.y; dst[2] = v.z; dst[3] = v.w;
        }
        __syncthreads();
#pragma unroll
        for (int jj = 0; jj < 2; jj++) {
            int rloc = jj*32 + tg;
            const float* dv = &dstm[rloc*65];
            float dot = 0.f;
#pragma unroll
            for (int d = 0; d < 64; d++) dot = fmaf(sv[d], dv[d], dot);
            int j = jt*64 + rloc;
            if (dot > best || (dot == best && j < bestj)) { best = dot; bestj = j; }
        }
    }
    // full-warp reduction (one warp = one src)
#pragma unroll
    for (int off = 1; off < 32; off <<= 1) {
        float ov = __shfl_xor_sync(0xffffffffu, best, off);
        int   oj = __shfl_xor_sync(0xffffffffu, bestj, off);
        if (ov > best || (ov == best && oj < bestj)) { best = ov; bestj = oj; }
    }
    if (tg == 0) {
        if (i == 0) { g_mask[0] = 0; g_node[0] = 0; }   // row 0 forced -inf
        else { g_mask[i] = (best > thr[0]) ? 1 : 0; g_node[i] = bestj; }
    }
}

// ---------------- exclusive prefix scan of !mask (warp-shuffle) ---------------
__global__ __launch_bounds__(1024) void scan_kernel()
{
    int tid = threadIdx.x;
    int lane = tid & 31, wid = tid >> 5;
    int f = g_mask[tid] ? 0 : 1;
    int v = f;
#pragma unroll
    for (int off = 1; off < 32; off <<= 1) {
        int u = __shfl_up_sync(0xffffffffu, v, off);
        if (lane >= off) v += u;
    }
    __shared__ int wsum[32];
    if (lane == 31) wsum[wid] = v;
    __syncthreads();
    if (wid == 0) {
        int wv = wsum[lane];
#pragma unroll
        for (int off = 1; off < 32; off <<= 1) {
            int u = __shfl_up_sync(0xffffffffu, wv, off);
            if (lane >= off) wv += u;
        }
        wsum[lane] = wv;
    }
    __syncthreads();
    int incl = v + (wid > 0 ? wsum[wid-1] : 0);
    g_pref[tid] = incl - f;
    if (tid == NSRC-1) g_nUnm[0] = incl;
}

// ---------------- fused merge build: dst rows (blocks 0..NSRC-1) +
//                  unmerged rows (blocks NSRC..2*NSRC-1) ----------------------
__global__ __launch_bounds__(256) void merge_build_kernel(const float* __restrict__ sizev)
{
    int b = blockIdx.x, tid = threadIdx.x;
    if (b >= NSRC) {
        // unmerged path
        int i = b - NSRC;
        if (g_mask[i]) return;
        int r = g_pref[i];
        float s = sizev[2*i];
        const float* xr = g_x1 + (size_t)(2*i) * CDIM;
        float* orow = g_outx + (size_t)r * CDIM;
        for (int c = tid; c < CDIM; c += 256) orow[c] = xr[c] * s;
        if (tid == 0) g_outs[r] = s;
        return;
    }

    // dst path
    __shared__ int   smask[NSRC];
    __shared__ int   snode[NSRC];
    __shared__ float ssize[NSRC];
    int j = b;
    for (int i = tid; i < NSRC; i += 256) {
        smask[i] = g_mask[i];
        snode[i] = g_node[i];
        ssize[i] = sizev[2*i];
    }
    __syncthreads();

    int nU = g_nUnm[0];
    float s0 = sizev[2*j + 1];
    const float* dr = g_x1 + (size_t)(2*j + 1) * CDIM;
    float a0 = dr[tid]       * s0;
    float a1 = dr[tid + 256] * s0;
    float a2 = dr[tid + 512] * s0;
    float a3 = dr[tid + 768] * s0;
    float stot = s0;
    for (int i = 0; i < NSRC; i++) {
        if (smask[i] && snode[i] == j) {
            float si = ssize[i];
            const float* xr = g_x1 + (size_t)(2*i) * CDIM;
            a0 += xr[tid]       * si;
            a1 += xr[tid + 256] * si;
            a2 += xr[tid + 512] * si;
            a3 += xr[tid + 768] * si;
            stot += si;
        }
    }
    size_t r = (size_t)(nU + j) * CDIM;
    g_outx[r + tid]       = a0;
    g_outx[r + tid + 256] = a1;
    g_outx[r + tid + 512] = a2;
    g_outx[r + tid + 768] = a3;
    if (tid == 0) g_outs[nU + j] = stot;
}

// ---------------- size tail --------------------------------------------------
__global__ __launch_bounds__(256) void size_tail_kernel(float* __restrict__ out, int Nout)
{
    int i = blockIdx.x * 256 + threadIdx.x;
    if (i < Nout) out[(size_t)Nout * CDIM + i] = g_outs[i];
}

// ---------------- launcher ---------------------------------------------------
extern "C" void kernel_launch(void* const* d_in, const int* in_sizes, int n_in,
                              void* d_out, int out_size)
{
    const float* x      = (const float*)d_in[0];
    const float* sizev  = (const float*)d_in[1];
    const float* qkv_w  = (const float*)d_in[2];
    const float* proj_w = (const float*)d_in[3];
    const float* proj_b = (const float*)d_in[4];
    const float* ln1_g  = (const float*)d_in[5];
    const float* ln1_b  = (const float*)d_in[6];
    const float* ln2_g  = (const float*)d_in[7];
    const float* ln2_b  = (const float*)d_in[8];
    const float* fc1_w  = (const float*)d_in[9];
    const float* fc1_b  = (const float*)d_in[10];
    const float* fc2_w  = (const float*)d_in[11];
    const float* fc2_b  = (const float*)d_in[12];
    const float* thr    = (const float*)d_in[13];
    float* out = (float*)d_out;

    int Nout, packSize;
    if (out_size % (CDIM + 1) == 0) { Nout = out_size / (CDIM + 1); packSize = 1; }
    else                            { Nout = out_size / CDIM;       packSize = 0; }
    if (Nout > NTOK) Nout = NTOK;

    float *p_h, *p_hr, *p_qkv, *p_xa, *p_x1, *p_x2, *p_h2, *p_ff;
    float *p_wqkv, *p_wproj, *p_wfc1, *p_wfc2;
    cudaGetSymbolAddress((void**)&p_h,    g_h);
    cudaGetSymbolAddress((void**)&p_hr,   g_hr);
    cudaGetSymbolAddress((void**)&p_qkv,  g_qkv);
    cudaGetSymbolAddress((void**)&p_xa,   g_xa);
    cudaGetSymbolAddress((void**)&p_x1,   g_x1);
    cudaGetSymbolAddress((void**)&p_x2,   g_x2);
    cudaGetSymbolAddress((void**)&p_h2,   g_h2);
    cudaGetSymbolAddress((void**)&p_ff,   g_ff);
    cudaGetSymbolAddress((void**)&p_wqkv, g_wqkv);
    cudaGetSymbolAddress((void**)&p_wproj,g_wproj);
    cudaGetSymbolAddress((void**)&p_wfc1, g_wfc1);
    cudaGetSymbolAddress((void**)&p_wfc2, g_wfc2);

    cudaFuncSetAttribute(attn_tc_kernel, cudaFuncAttributeMaxDynamicSharedMemorySize, ATTN_SMEM_B);
    cudaFuncSetAttribute(gemm_tf32<0,1>, cudaFuncAttributeMaxDynamicSharedMemorySize, GEMM_SMEM);
    cudaFuncSetAttribute(gemm_tf32<2,1>, cudaFuncAttributeMaxDynamicSharedMemorySize, GEMM_SMEM);
    cudaFuncSetAttribute(gemm_tf32<3,0>, cudaFuncAttributeMaxDynamicSharedMemorySize, GEMM_SMEM);

    // 0. pre-round all four weight matrices + log(size) precompute
    round4_kernel<<<(N4_ALL + 255)/256, 256>>>(qkv_w, proj_w, fc1_w, fc2_w);
    log_kernel<<<(NTOK + 255)/256, 256>>>(sizev);
    // 1. LN1: exact h (metric) + rounded hr (GEMM)
    ln_kernel<<<NTOK, 256>>>(x, ln1_g, ln1_b, p_h, p_hr, NTOK);
    // 2a. averaged K-weights (fp32 merge-metric firewall)
    wkavg_kernel<<<(CDIM*DH + 255)/256, 256>>>(qkv_w);
    // 2b. QKV = hr @ wqkv, output rounded to tf32
    gemm_tf32<0,1><<<dim3(3*CDIM/128, NTOK/128), 128, GEMM_SMEM>>>(
        p_hr, p_wqkv, nullptr, nullptr, p_qkv, NTOK, 3*CDIM, CDIM);
    // 3. metric = normalize(h @ wkavg)  (fp32 split-K x8, exact mask decisions)
    metric_gemm_kernel<<<dim3(NTOK/64, 8), 256>>>();
    metric_norm_kernel<<<NTOK/8, 256>>>();
    // 4. attention -> xa (rounded)  (tf32 TC, 128q/CTA, Q-in-regs, 2 CTAs/SM)
    attn_tc_kernel<<<dim3(NTOK/128, HEADS), 256, ATTN_SMEM_B>>>(p_qkv, p_xa);
    // 5. x1 = x + xa @ wproj + proj_b  (tf32)
    gemm_tf32<3,0><<<dim3(CDIM/128, NTOK/128), 128, GEMM_SMEM>>>(
        p_xa, p_wproj, proj_b, x, p_x1, NTOK, CDIM, CDIM);
    // 6. merge scores (128 blocks, warp-per-src)
    merge_score_kernel<<<NSRC/8, 256>>>(thr);
    // 7. prefix scan (warp-shuffle)
    scan_kernel<<<1, 1024>>>();
    // 8+9. fused: dst rows + unmerged rows
    merge_build_kernel<<<2*NSRC, 256>>>(sizev);
    // 10+11. fused x2 = outx/size, LN2 -> rounded h2
    divln_kernel<<<Nout, 256>>>(ln2_g, ln2_b, Nout);
    // 12. ff = round(gelu(h2 @ wfc1 + fc1_b))  (tf32)
    gemm_tf32<2,1><<<dim3(FF/128, (Nout + 127)/128), 128, GEMM_SMEM>>>(
        p_h2, p_wfc1, fc1_b, nullptr, p_ff, Nout, FF, CDIM);
    // 13. out = x2 + ff @ wfc2 + fc2_b  (tf32, writes d_out directly)
    gemm_tf32<3,0><<<dim3(CDIM/128, (Nout + 127)/128), 128, GEMM_SMEM>>>(
        p_ff, p_wfc2, fc2_b, p_x2, out, Nout, CDIM, FF);
    // 14. append sizes
    if (packSize)
        size_tail_kernel<<<(Nout + 255)/256, 256>>>(out, Nout);
}